// round 3
// baseline (speedup 1.0000x reference)
#include <cuda_runtime.h>
#include <math.h>
#include <stdint.h>

#define B_  2
#define T_  1024
#define D_  2048
#define H_  16
#define KVH_ 4
#define DH_ 128
#define REP_ 4

#define LAMBDA_INIT_F   0.35550906759096927f
#define ONE_MINUS_LI_F  0.64449093240903073f
#define GN_EPS_F        1e-5f
#define SCALE_F         0.08838834764831845f  // 1/sqrt(128)

#define BK   16
#define PADK 20   // stride pad: (row*20+col) mod 32 distinct for 8x4 frag pattern

// ---------------- scratch ----------------------------------------------------
static __device__ float g_Q[(size_t)B_*T_*H_*2*DH_];    // (2048, 4096)
static __device__ float g_K[(size_t)B_*T_*KVH_*2*DH_];  // (2048, 1024)
static __device__ float g_V[(size_t)B_*T_*KVH_*2*DH_];  // (2048, 1024)
static __device__ float g_O[(size_t)B_*T_*H_*2*DH_];    // (2048, 4096)
static __device__ float g_lambda;

// ---------------- helpers ----------------------------------------------------
__device__ __forceinline__ float to_tf32(float x) {
    float r;
    asm("cvt.rna.tf32.f32 %0, %1;" : "=f"(r) : "f"(x));
    return r;
}
__device__ __forceinline__ float4 to_tf32_4(float4 v) {
    v.x = to_tf32(v.x); v.y = to_tf32(v.y);
    v.z = to_tf32(v.z); v.w = to_tf32(v.w);
    return v;
}

__device__ __forceinline__ void mma_tf32(float* c, const uint32_t* a, const uint32_t* b) {
    asm volatile(
        "mma.sync.aligned.m16n8k8.row.col.f32.tf32.tf32.f32 "
        "{%0,%1,%2,%3}, {%4,%5,%6,%7}, {%8,%9}, {%0,%1,%2,%3};"
        : "+f"(c[0]), "+f"(c[1]), "+f"(c[2]), "+f"(c[3])
        : "r"(a[0]), "r"(a[1]), "r"(a[2]), "r"(a[3]), "r"(b[0]), "r"(b[1]));
}

// ---------------- lambda scalar ----------------------------------------------
__global__ void lambda_kernel(const float* __restrict__ lq1, const float* __restrict__ lk1,
                              const float* __restrict__ lq2, const float* __restrict__ lk2) {
    int lane = threadIdx.x;
    float d1 = 0.f, d2 = 0.f;
    #pragma unroll
    for (int i = 0; i < 4; i++) {
        int idx = lane * 4 + i;
        d1 += lq1[idx] * lk1[idx];
        d2 += lq2[idx] * lk2[idx];
    }
    #pragma unroll
    for (int o = 16; o; o >>= 1) {
        d1 += __shfl_xor_sync(0xffffffffu, d1, o);
        d2 += __shfl_xor_sync(0xffffffffu, d2, o);
    }
    if (lane == 0)
        g_lambda = expf(d1) - expf(d2) + LAMBDA_INIT_F;
}

// ---------------- double-buffered tf32 GEMM body -----------------------------
// C[128,128] tile = A[128,K] @ W[128,K]^T, 256 thr = 8 warps (2M x 4N), warp 64x32
__device__ __forceinline__ void gemm_body(
    const float* __restrict__ Ablk,   // A + bm*K
    const float* __restrict__ Bblk,   // W + bn*K
    float* __restrict__ Cblk,         // C + bm*ldc + bn
    int K, int ldc,
    float (*As)[128][PADK], float (*Bs)[128][PADK])
{
    const int tid  = threadIdx.x;
    const int warp = tid >> 5;
    const int lane = tid & 31;
    const int wm = (warp >> 2) * 64;
    const int wn = (warp & 3) * 32;
    const int lr = lane >> 2;
    const int lc = lane & 3;

    // loader mapping: idx in [0,512): row=idx>>2, col=(idx&3)*4
    const int l_row0 = tid >> 2;
    const int l_col  = (tid & 3) * 4;
    const int l_row1 = (tid + 256) >> 2;

    float acc[4][4][4];
    #pragma unroll
    for (int mi = 0; mi < 4; mi++)
        #pragma unroll
        for (int ni = 0; ni < 4; ni++)
            #pragma unroll
            for (int r = 0; r < 4; r++)
                acc[mi][ni][r] = 0.f;

    const int nt = K / BK;
    float4 sa0, sa1, sb0, sb1;

    // prologue: load tile 0 into regs, store stage 0
    sa0 = *(const float4*)&Ablk[(size_t)l_row0 * K + l_col];
    sa1 = *(const float4*)&Ablk[(size_t)l_row1 * K + l_col];
    sb0 = *(const float4*)&Bblk[(size_t)l_row0 * K + l_col];
    sb1 = *(const float4*)&Bblk[(size_t)l_row1 * K + l_col];
    *(float4*)&As[0][l_row0][l_col] = to_tf32_4(sa0);
    *(float4*)&As[0][l_row1][l_col] = to_tf32_4(sa1);
    *(float4*)&Bs[0][l_row0][l_col] = to_tf32_4(sb0);
    *(float4*)&Bs[0][l_row1][l_col] = to_tf32_4(sb1);
    __syncthreads();

    for (int t = 0; t < nt; t++) {
        const int s = t & 1;
        if (t + 1 < nt) {
            const int k0 = (t + 1) * BK;
            sa0 = *(const float4*)&Ablk[(size_t)l_row0 * K + k0 + l_col];
            sa1 = *(const float4*)&Ablk[(size_t)l_row1 * K + k0 + l_col];
            sb0 = *(const float4*)&Bblk[(size_t)l_row0 * K + k0 + l_col];
            sb1 = *(const float4*)&Bblk[(size_t)l_row1 * K + k0 + l_col];
        }

        #pragma unroll
        for (int kk = 0; kk < 2; kk++) {
            uint32_t af[4][4], bf[4][2];
            #pragma unroll
            for (int mi = 0; mi < 4; mi++) {
                af[mi][0] = __float_as_uint(As[s][wm + mi * 16 + lr]    [kk * 8 + lc]);
                af[mi][1] = __float_as_uint(As[s][wm + mi * 16 + lr + 8][kk * 8 + lc]);
                af[mi][2] = __float_as_uint(As[s][wm + mi * 16 + lr]    [kk * 8 + lc + 4]);
                af[mi][3] = __float_as_uint(As[s][wm + mi * 16 + lr + 8][kk * 8 + lc + 4]);
            }
            #pragma unroll
            for (int ni = 0; ni < 4; ni++) {
                bf[ni][0] = __float_as_uint(Bs[s][wn + ni * 8 + lr][kk * 8 + lc]);
                bf[ni][1] = __float_as_uint(Bs[s][wn + ni * 8 + lr][kk * 8 + lc + 4]);
            }
            #pragma unroll
            for (int mi = 0; mi < 4; mi++)
                #pragma unroll
                for (int ni = 0; ni < 4; ni++)
                    mma_tf32(acc[mi][ni], af[mi], bf[ni]);
        }

        if (t + 1 < nt) {
            const int s1 = s ^ 1;
            *(float4*)&As[s1][l_row0][l_col] = to_tf32_4(sa0);
            *(float4*)&As[s1][l_row1][l_col] = to_tf32_4(sa1);
            *(float4*)&Bs[s1][l_row0][l_col] = to_tf32_4(sb0);
            *(float4*)&Bs[s1][l_row1][l_col] = to_tf32_4(sb1);
        }
        __syncthreads();
    }

    #pragma unroll
    for (int mi = 0; mi < 4; mi++) {
        #pragma unroll
        for (int ni = 0; ni < 4; ni++) {
            int r0 = wm + mi * 16 + lr;
            int cc = wn + ni * 8 + 2 * lc;
            *(float2*)&Cblk[(size_t)r0 * ldc + cc] =
                make_float2(acc[mi][ni][0], acc[mi][ni][1]);
            *(float2*)&Cblk[(size_t)(r0 + 8) * ldc + cc] =
                make_float2(acc[mi][ni][2], acc[mi][ni][3]);
        }
    }
}

// ---------------- fused QKV projection ----------------------------------------
// grid (48, 16): bx 0..31 -> Q cols, 32..39 -> K, 40..47 -> V
__global__ void __launch_bounds__(256, 2) gemm_qkv(const float* __restrict__ x,
                                                   const float* __restrict__ Wq,
                                                   const float* __restrict__ Wk,
                                                   const float* __restrict__ Wv,
                                                   float* __restrict__ Q,
                                                   float* __restrict__ K,
                                                   float* __restrict__ V) {
    __shared__ float As[2][128][PADK];
    __shared__ float Bs[2][128][PADK];

    const int bx = blockIdx.x;
    const int bm = blockIdx.y * 128;
    const float* W;
    float* C;
    int ldc, bn;
    if (bx < 32)      { W = Wq; C = Q; ldc = 4096; bn = bx * 128; }
    else if (bx < 40) { W = Wk; C = K; ldc = 1024; bn = (bx - 32) * 128; }
    else              { W = Wv; C = V; ldc = 1024; bn = (bx - 40) * 128; }

    gemm_body(x + (size_t)bm * D_, W + (size_t)bn * D_,
              C + (size_t)bm * ldc + bn, D_, ldc, As, Bs);
}

// ---------------- generic GEMM (output projection) ----------------------------
__global__ void __launch_bounds__(256, 2) gemm_nt_db(const float* __restrict__ A,
                                                     const float* __restrict__ W,
                                                     float* __restrict__ C,
                                                     int N, int K) {
    __shared__ float As[2][128][PADK];
    __shared__ float Bs[2][128][PADK];
    const int bm = blockIdx.y * 128;
    const int bn = blockIdx.x * 128;
    gemm_body(A + (size_t)bm * K, W + (size_t)bn * K,
              C + (size_t)bm * N + bn, K, N, As, Bs);
}

// ---------------- RoPE (in place) ---------------------------------------------
__global__ void rope_kernel(float* __restrict__ X, const int* __restrict__ pos,
                            int nheads2, int npairs_total) {
    int idx = blockIdx.x * blockDim.x + threadIdx.x;
    if (idx >= npairs_total) return;
    int i = idx & 63;
    int row = idx >> 6;
    int t = (row / nheads2) % T_;
    // 10000^(-2i/128) = exp2(-(2i/128)*log2(10000))
    float inv = exp2f((float)i * (-13.287712379549449f / 64.0f));
    float ang = (float)pos[t] * inv;
    float s, c;
    sincosf(ang, &s, &c);
    float* p = X + (size_t)row * 128 + 2 * i;
    float x1 = p[0], x2 = p[1];
    p[0] = x1 * c - x2 * s;
    p[1] = x1 * s + x2 * c;
}

// ---------------- dual-softmax flash attention + diff + GroupNorm -------------
__global__ void __launch_bounds__(256) attn_kernel(const float* __restrict__ Q,
                                                   const float* __restrict__ Kg,
                                                   const float* __restrict__ Vg,
                                                   float* __restrict__ O,
                                                   const float* __restrict__ gnw,
                                                   const float* __restrict__ gnb) {
    __shared__ float k1s[16][128];
    __shared__ float k2s[16][128];
    __shared__ float vs[16][256];

    const int bh = blockIdx.y;
    const int b = bh / H_;
    const int h = bh % H_;
    const int kvh = h / REP_;
    const int warp = threadIdx.x >> 5;
    const int lane = threadIdx.x & 31;
    const int q = blockIdx.x * 8 + warp;

    const size_t qbase = ((size_t)(b * T_ + q) * H_ + h) * 256;
    const float4 q1v = *(const float4*)&Q[qbase + lane * 4];
    const float4 q2v = *(const float4*)&Q[qbase + 128 + lane * 4];

    float m1 = -1e30f, m2 = -1e30f, l1 = 0.f, l2 = 0.f;
    float acc1[8], acc2[8];
    #pragma unroll
    for (int m = 0; m < 8; m++) { acc1[m] = 0.f; acc2[m] = 0.f; }

    const int q_hi = blockIdx.x * 8 + 7;
    const int ntiles = q_hi / 16 + 1;

    for (int kt = 0; kt < ntiles; kt++) {
        const int j0 = kt * 16;
        __syncthreads();
        for (int i = threadIdx.x; i < 16 * 64; i += 256) {
            int j = i >> 6;
            int c4 = i & 63;
            size_t kb = ((size_t)(b * T_ + j0 + j) * KVH_ + kvh) * 256;
            float4 kv = *(const float4*)&Kg[kb + c4 * 4];
            if (c4 < 32) *(float4*)&k1s[j][c4 * 4] = kv;
            else         *(float4*)&k2s[j][(c4 - 32) * 4] = kv;
            float4 vv = *(const float4*)&Vg[kb + c4 * 4];
            *(float4*)&vs[j][c4 * 4] = vv;
        }
        __syncthreads();

        const int jmax = min(15, q - j0);
        for (int jj = 0; jj <= jmax; jj++) {
            float4 k1v = *(const float4*)&k1s[jj][lane * 4];
            float4 k2v = *(const float4*)&k2s[jj][lane * 4];
            float d1 = q1v.x * k1v.x + q1v.y * k1v.y + q1v.z * k1v.z + q1v.w * k1v.w;
            float d2 = q2v.x * k2v.x + q2v.y * k2v.y + q2v.z * k2v.z + q2v.w * k2v.w;
            #pragma unroll
            for (int o = 16; o; o >>= 1) {
                d1 += __shfl_xor_sync(0xffffffffu, d1, o);
                d2 += __shfl_xor_sync(0xffffffffu, d2, o);
            }
            float s1 = d1 * SCALE_F;
            float s2 = d2 * SCALE_F;
            float m1n = fmaxf(m1, s1), m2n = fmaxf(m2, s2);
            float c1 = __expf(m1 - m1n), c2 = __expf(m2 - m2n);
            float p1 = __expf(s1 - m1n), p2 = __expf(s2 - m2n);
            l1 = l1 * c1 + p1;
            l2 = l2 * c2 + p2;
            m1 = m1n; m2 = m2n;
            #pragma unroll
            for (int m = 0; m < 8; m++) {
                float vv = vs[jj][lane + 32 * m];
                acc1[m] = acc1[m] * c1 + p1 * vv;
                acc2[m] = acc2[m] * c2 + p2 * vv;
            }
        }
    }

    const float lam = g_lambda;
    const float r1 = 1.f / l1;
    const float r2 = lam / l2;
    float o[8];
    float sum = 0.f, sumsq = 0.f;
    #pragma unroll
    for (int m = 0; m < 8; m++) {
        o[m] = acc1[m] * r1 - acc2[m] * r2;
        sum += o[m];
        sumsq += o[m] * o[m];
    }
    #pragma unroll
    for (int off = 16; off; off >>= 1) {
        sum   += __shfl_xor_sync(0xffffffffu, sum, off);
        sumsq += __shfl_xor_sync(0xffffffffu, sumsq, off);
    }
    const float mean = sum * (1.f / 256.f);
    const float var = sumsq * (1.f / 256.f) - mean * mean;
    const float rstd = rsqrtf(var + GN_EPS_F);

    const size_t obase = (size_t)(b * T_ + q) * 4096 + h * 256;
    #pragma unroll
    for (int m = 0; m < 8; m++) {
        int c = lane + 32 * m;
        float val = (o[m] - mean) * rstd * gnw[h * 256 + c] + gnb[h * 256 + c];
        O[obase + c] = val * ONE_MINUS_LI_F;
    }
}

// ---------------- host launcher -----------------------------------------------
extern "C" void kernel_launch(void* const* d_in, const int* in_sizes, int n_in,
                              void* d_out, int out_size) {
    const float* x   = (const float*)d_in[0];
    const float* Wq  = (const float*)d_in[1];
    const float* Wk  = (const float*)d_in[2];
    const float* Wv  = (const float*)d_in[3];
    const float* Wo  = (const float*)d_in[4];
    const float* lq1 = (const float*)d_in[5];
    const float* lk1 = (const float*)d_in[6];
    const float* lq2 = (const float*)d_in[7];
    const float* lk2 = (const float*)d_in[8];
    const float* gnw = (const float*)d_in[9];
    const float* gnb = (const float*)d_in[10];
    const int*   pos = (const int*)d_in[11];
    float* out = (float*)d_out;

    float *pQ, *pK, *pV, *pO;
    cudaGetSymbolAddress((void**)&pQ, g_Q);
    cudaGetSymbolAddress((void**)&pK, g_K);
    cudaGetSymbolAddress((void**)&pV, g_V);
    cudaGetSymbolAddress((void**)&pO, g_O);

    const int M = B_ * T_;   // 2048

    lambda_kernel<<<1, 32>>>(lq1, lk1, lq2, lk2);

    // fused Q/K/V projections
    gemm_qkv<<<dim3(48, M / 128), 256>>>(x, Wq, Wk, Wv, pQ, pK, pV);

    // RoPE in place
    {
        int npq = M * H_ * 2 * 64;
        int npk = M * KVH_ * 2 * 64;
        rope_kernel<<<(npq + 255) / 256, 256>>>(pQ, pos, 2 * H_, npq);
        rope_kernel<<<(npk + 255) / 256, 256>>>(pK, pos, 2 * KVH_, npk);
    }

    // attention + diff combine + GroupNorm
    attn_kernel<<<dim3(T_ / 8, B_ * H_), 256>>>(pQ, pK, pV, pO, gnw, gnb);

    // output projection
    gemm_nt_db<<<dim3(D_ / 128, M / 128), 256>>>(pO, Wo, out, D_, 4096);
}

// round 4
// speedup vs baseline: 2.3172x; 2.3172x over previous
#include <cuda_runtime.h>
#include <math.h>
#include <stdint.h>

#define B_  2
#define T_  1024
#define D_  2048
#define H_  16
#define KVH_ 4
#define DH_ 128
#define REP_ 4

#define LAMBDA_INIT_F   0.35550906759096927f
#define ONE_MINUS_LI_F  0.64449093240903073f
#define GN_EPS_F        1e-5f
#define SCALE_F         0.08838834764831845f  // 1/sqrt(128)

#define BK   16
#define PADK 20

// ---------------- scratch ----------------------------------------------------
static __device__ float g_Q[(size_t)B_*T_*H_*2*DH_];    // (2048, 4096)
static __device__ float g_K[(size_t)B_*T_*KVH_*2*DH_];  // (2048, 1024)
static __device__ float g_V[(size_t)B_*T_*KVH_*2*DH_];  // (2048, 1024)
static __device__ float g_O[(size_t)B_*T_*H_*2*DH_];    // (2048, 4096)
static __device__ float g_lambda;

// ---------------- helpers ----------------------------------------------------
__device__ __forceinline__ float to_tf32(float x) {
    float r;
    asm("cvt.rna.tf32.f32 %0, %1;" : "=f"(r) : "f"(x));
    return r;
}
__device__ __forceinline__ float4 to_tf32_4(float4 v) {
    v.x = to_tf32(v.x); v.y = to_tf32(v.y);
    v.z = to_tf32(v.z); v.w = to_tf32(v.w);
    return v;
}
__device__ __forceinline__ void mma_tf32(float* c, const uint32_t* a, const uint32_t* b) {
    asm volatile(
        "mma.sync.aligned.m16n8k8.row.col.f32.tf32.tf32.f32 "
        "{%0,%1,%2,%3}, {%4,%5,%6,%7}, {%8,%9}, {%0,%1,%2,%3};"
        : "+f"(c[0]), "+f"(c[1]), "+f"(c[2]), "+f"(c[3])
        : "r"(a[0]), "r"(a[1]), "r"(a[2]), "r"(a[3]), "r"(b[0]), "r"(b[1]));
}

// ---------------- lambda scalar ----------------------------------------------
__global__ void lambda_kernel(const float* __restrict__ lq1, const float* __restrict__ lk1,
                              const float* __restrict__ lq2, const float* __restrict__ lk2) {
    int lane = threadIdx.x;
    float d1 = 0.f, d2 = 0.f;
    #pragma unroll
    for (int i = 0; i < 4; i++) {
        int idx = lane * 4 + i;
        d1 += lq1[idx] * lk1[idx];
        d2 += lq2[idx] * lk2[idx];
    }
    #pragma unroll
    for (int o = 16; o; o >>= 1) {
        d1 += __shfl_xor_sync(0xffffffffu, d1, o);
        d2 += __shfl_xor_sync(0xffffffffu, d2, o);
    }
    if (lane == 0)
        g_lambda = expf(d1) - expf(d2) + LAMBDA_INIT_F;
}

// ---------------- double-buffered tf32 GEMM body -----------------------------
__device__ __forceinline__ void gemm_body(
    const float* __restrict__ Ablk, const float* __restrict__ Bblk,
    float* __restrict__ Cblk, int K, int ldc,
    float (*As)[128][PADK], float (*Bs)[128][PADK])
{
    const int tid  = threadIdx.x;
    const int warp = tid >> 5;
    const int lane = tid & 31;
    const int wm = (warp >> 2) * 64;
    const int wn = (warp & 3) * 32;
    const int lr = lane >> 2;
    const int lc = lane & 3;

    const int l_row0 = tid >> 2;
    const int l_col  = (tid & 3) * 4;
    const int l_row1 = (tid + 256) >> 2;

    float acc[4][4][4];
    #pragma unroll
    for (int mi = 0; mi < 4; mi++)
        #pragma unroll
        for (int ni = 0; ni < 4; ni++)
            #pragma unroll
            for (int r = 0; r < 4; r++)
                acc[mi][ni][r] = 0.f;

    const int nt = K / BK;
    float4 sa0, sa1, sb0, sb1;

    sa0 = *(const float4*)&Ablk[(size_t)l_row0 * K + l_col];
    sa1 = *(const float4*)&Ablk[(size_t)l_row1 * K + l_col];
    sb0 = *(const float4*)&Bblk[(size_t)l_row0 * K + l_col];
    sb1 = *(const float4*)&Bblk[(size_t)l_row1 * K + l_col];
    *(float4*)&As[0][l_row0][l_col] = to_tf32_4(sa0);
    *(float4*)&As[0][l_row1][l_col] = to_tf32_4(sa1);
    *(float4*)&Bs[0][l_row0][l_col] = to_tf32_4(sb0);
    *(float4*)&Bs[0][l_row1][l_col] = to_tf32_4(sb1);
    __syncthreads();

    for (int t = 0; t < nt; t++) {
        const int s = t & 1;
        if (t + 1 < nt) {
            const int k0 = (t + 1) * BK;
            sa0 = *(const float4*)&Ablk[(size_t)l_row0 * K + k0 + l_col];
            sa1 = *(const float4*)&Ablk[(size_t)l_row1 * K + k0 + l_col];
            sb0 = *(const float4*)&Bblk[(size_t)l_row0 * K + k0 + l_col];
            sb1 = *(const float4*)&Bblk[(size_t)l_row1 * K + k0 + l_col];
        }
        #pragma unroll
        for (int kk = 0; kk < 2; kk++) {
            uint32_t af[4][4], bf[4][2];
            #pragma unroll
            for (int mi = 0; mi < 4; mi++) {
                af[mi][0] = __float_as_uint(As[s][wm + mi * 16 + lr]    [kk * 8 + lc]);
                af[mi][1] = __float_as_uint(As[s][wm + mi * 16 + lr + 8][kk * 8 + lc]);
                af[mi][2] = __float_as_uint(As[s][wm + mi * 16 + lr]    [kk * 8 + lc + 4]);
                af[mi][3] = __float_as_uint(As[s][wm + mi * 16 + lr + 8][kk * 8 + lc + 4]);
            }
            #pragma unroll
            for (int ni = 0; ni < 4; ni++) {
                bf[ni][0] = __float_as_uint(Bs[s][wn + ni * 8 + lr][kk * 8 + lc]);
                bf[ni][1] = __float_as_uint(Bs[s][wn + ni * 8 + lr][kk * 8 + lc + 4]);
            }
            #pragma unroll
            for (int mi = 0; mi < 4; mi++)
                #pragma unroll
                for (int ni = 0; ni < 4; ni++)
                    mma_tf32(acc[mi][ni], af[mi], bf[ni]);
        }
        if (t + 1 < nt) {
            const int s1 = s ^ 1;
            *(float4*)&As[s1][l_row0][l_col] = to_tf32_4(sa0);
            *(float4*)&As[s1][l_row1][l_col] = to_tf32_4(sa1);
            *(float4*)&Bs[s1][l_row0][l_col] = to_tf32_4(sb0);
            *(float4*)&Bs[s1][l_row1][l_col] = to_tf32_4(sb1);
        }
        __syncthreads();
    }

    #pragma unroll
    for (int mi = 0; mi < 4; mi++) {
        #pragma unroll
        for (int ni = 0; ni < 4; ni++) {
            int r0 = wm + mi * 16 + lr;
            int cc = wn + ni * 8 + 2 * lc;
            *(float2*)&Cblk[(size_t)r0 * ldc + cc] =
                make_float2(acc[mi][ni][0], acc[mi][ni][1]);
            *(float2*)&Cblk[(size_t)(r0 + 8) * ldc + cc] =
                make_float2(acc[mi][ni][2], acc[mi][ni][3]);
        }
    }
}

__global__ void __launch_bounds__(256, 2) gemm_qkv(const float* __restrict__ x,
                                                   const float* __restrict__ Wq,
                                                   const float* __restrict__ Wk,
                                                   const float* __restrict__ Wv,
                                                   float* __restrict__ Q,
                                                   float* __restrict__ K,
                                                   float* __restrict__ V) {
    __shared__ float As[2][128][PADK];
    __shared__ float Bs[2][128][PADK];
    const int bx = blockIdx.x;
    const int bm = blockIdx.y * 128;
    const float* W; float* C; int ldc, bn;
    if (bx < 32)      { W = Wq; C = Q; ldc = 4096; bn = bx * 128; }
    else if (bx < 40) { W = Wk; C = K; ldc = 1024; bn = (bx - 32) * 128; }
    else              { W = Wv; C = V; ldc = 1024; bn = (bx - 40) * 128; }
    gemm_body(x + (size_t)bm * D_, W + (size_t)bn * D_,
              C + (size_t)bm * ldc + bn, D_, ldc, As, Bs);
}

__global__ void __launch_bounds__(256, 2) gemm_nt_db(const float* __restrict__ A,
                                                     const float* __restrict__ W,
                                                     float* __restrict__ C,
                                                     int N, int K) {
    __shared__ float As[2][128][PADK];
    __shared__ float Bs[2][128][PADK];
    const int bm = blockIdx.y * 128;
    const int bn = blockIdx.x * 128;
    gemm_body(A + (size_t)bm * K, W + (size_t)bn * K,
              C + (size_t)bm * N + bn, K, N, As, Bs);
}

// ---------------- RoPE (in place) ---------------------------------------------
__global__ void rope_kernel(float* __restrict__ X, const int* __restrict__ pos,
                            int nheads2, int npairs_total) {
    int idx = blockIdx.x * blockDim.x + threadIdx.x;
    if (idx >= npairs_total) return;
    int i = idx & 63;
    int row = idx >> 6;
    int t = (row / nheads2) % T_;
    float inv = exp2f((float)i * (-13.287712379549449f / 64.0f));
    float ang = (float)pos[t] * inv;
    float s, c;
    sincosf(ang, &s, &c);
    float* p = X + (size_t)row * 128 + 2 * i;
    float x1 = p[0], x2 = p[1];
    p[0] = x1 * c - x2 * s;
    p[1] = x1 * s + x2 * c;
}

// ---------------- tensor-core dual flash attention + diff + GroupNorm ---------
// CTA: 32 queries of one (b,h). 8 warps: branch(2) x rowgroup(2) x vhalf(2).
// smem (floats): K1s[32][132] | K2s[32][132] | Vs[32][264] | Psm[8][16][36]
// QS[32][260] aliases K1s+K2s at prologue; Osm[32][264] aliases at epilogue.
#define SM_K1 0
#define SM_K2 4224
#define SM_V  8448
#define SM_P  16896
#define SM_TOTF 21504

__global__ void __launch_bounds__(256) attn_kernel(const float* __restrict__ Q,
                                                   const float* __restrict__ Kg,
                                                   const float* __restrict__ Vg,
                                                   float* __restrict__ O,
                                                   const float* __restrict__ gnw,
                                                   const float* __restrict__ gnb) {
    extern __shared__ float smem[];
    float (*K1s)[132] = (float(*)[132])(smem + SM_K1);
    float (*K2s)[132] = (float(*)[132])(smem + SM_K2);
    float (*Vs)[264]  = (float(*)[264])(smem + SM_V);
    float (*QS)[260]  = (float(*)[260])smem;
    float (*Osm)[264] = (float(*)[264])smem;

    const int tid  = threadIdx.x;
    const int warp = tid >> 5;
    const int lane = tid & 31;
    const int lr = lane >> 2;      // 0..7
    const int lc = lane & 3;       // 0..3
    const int br = warp >> 2;      // branch 0/1
    const int rg = (warp >> 1) & 1;
    const int vh = warp & 1;

    float (*Psm)[36] = (float(*)[36])(smem + SM_P + warp * 576);

    const int bh = blockIdx.y;
    const int b = bh / H_;
    const int h = bh % H_;
    const int kvh = h / REP_;
    const int q0 = blockIdx.x * 32;

    // ---- stage Q (scaled, tf32) into QS, then pull A-frags ----
    #pragma unroll
    for (int r = 0; r < 8; r++) {
        int idx = tid + 256 * r;
        int qr = idx >> 6;
        int c4 = (idx & 63) * 4;
        float4 v = *(const float4*)&Q[((size_t)(b * T_ + q0 + qr) * H_ + h) * 256 + c4];
        v.x *= SCALE_F; v.y *= SCALE_F; v.z *= SCALE_F; v.w *= SCALE_F;
        *(float4*)&QS[qr][c4] = to_tf32_4(v);
    }
    __syncthreads();

    uint32_t qf[16][4];
    {
        const int r0 = rg * 16 + lr;
        const int cb = br * 128;
        #pragma unroll
        for (int ks = 0; ks < 16; ks++) {
            qf[ks][0] = __float_as_uint(QS[r0]    [cb + ks * 8 + lc]);
            qf[ks][1] = __float_as_uint(QS[r0 + 8][cb + ks * 8 + lc]);
            qf[ks][2] = __float_as_uint(QS[r0]    [cb + ks * 8 + lc + 4]);
            qf[ks][3] = __float_as_uint(QS[r0 + 8][cb + ks * 8 + lc + 4]);
        }
    }

    float oacc[16][4];
    #pragma unroll
    for (int n = 0; n < 16; n++)
        #pragma unroll
        for (int r = 0; r < 4; r++)
            oacc[n][r] = 0.f;
    float m0 = -1e30f, m1 = -1e30f, l0 = 0.f, l1 = 0.f;

    const float (*Ks)[132] = br ? K2s : K1s;
    const int row0 = q0 + rg * 16 + lr;
    const int row1 = row0 + 8;
    const int ntiles = q0 / 32 + 1;

    for (int kt = 0; kt < ntiles; kt++) {
        const int k0 = kt * 32;
        __syncthreads();
        // cooperative K1/K2/V tile load (tf32)
        #pragma unroll
        for (int r = 0; r < 8; r++) {
            int idx = tid + 256 * r;
            int j = idx >> 6;
            int c4 = idx & 63;
            size_t kb = ((size_t)(b * T_ + k0 + j) * KVH_ + kvh) * 256;
            float4 kv = to_tf32_4(*(const float4*)&Kg[kb + c4 * 4]);
            if (c4 < 32) *(float4*)&K1s[j][c4 * 4] = kv;
            else         *(float4*)&K2s[j][(c4 - 32) * 4] = kv;
            float4 vv = to_tf32_4(*(const float4*)&Vg[kb + c4 * 4]);
            *(float4*)&Vs[j][c4 * 4] = vv;
        }
        __syncthreads();

        // ---- S = Qbr @ Kbr^T  [16 x 32] ----
        float sf[4][4];
        #pragma unroll
        for (int n = 0; n < 4; n++)
            #pragma unroll
            for (int r = 0; r < 4; r++)
                sf[n][r] = 0.f;
        #pragma unroll
        for (int n = 0; n < 4; n++) {
            #pragma unroll
            for (int ks = 0; ks < 16; ks++) {
                uint32_t bf[2];
                bf[0] = __float_as_uint(Ks[n * 8 + lr][ks * 8 + lc]);
                bf[1] = __float_as_uint(Ks[n * 8 + lr][ks * 8 + lc + 4]);
                mma_tf32(sf[n], qf[ks], bf);
            }
        }

        // ---- causal mask (diagonal tile only) ----
        if (kt == ntiles - 1) {
            #pragma unroll
            for (int n = 0; n < 4; n++) {
                int key = k0 + n * 8 + 2 * lc;
                if (key     > row0) sf[n][0] = -1e30f;
                if (key + 1 > row0) sf[n][1] = -1e30f;
                if (key     > row1) sf[n][2] = -1e30f;
                if (key + 1 > row1) sf[n][3] = -1e30f;
            }
        }

        // ---- online softmax ----
        float mx0 = -1e30f, mx1 = -1e30f;
        #pragma unroll
        for (int n = 0; n < 4; n++) {
            mx0 = fmaxf(mx0, fmaxf(sf[n][0], sf[n][1]));
            mx1 = fmaxf(mx1, fmaxf(sf[n][2], sf[n][3]));
        }
        mx0 = fmaxf(mx0, __shfl_xor_sync(0xffffffffu, mx0, 1));
        mx0 = fmaxf(mx0, __shfl_xor_sync(0xffffffffu, mx0, 2));
        mx1 = fmaxf(mx1, __shfl_xor_sync(0xffffffffu, mx1, 1));
        mx1 = fmaxf(mx1, __shfl_xor_sync(0xffffffffu, mx1, 2));

        float mn0 = fmaxf(m0, mx0), mn1 = fmaxf(m1, mx1);
        float c0 = __expf(m0 - mn0), c1 = __expf(m1 - mn1);
        m0 = mn0; m1 = mn1;

        float rs0 = 0.f, rs1 = 0.f;
        #pragma unroll
        for (int n = 0; n < 4; n++) {
            sf[n][0] = __expf(sf[n][0] - mn0);
            sf[n][1] = __expf(sf[n][1] - mn0);
            sf[n][2] = __expf(sf[n][2] - mn1);
            sf[n][3] = __expf(sf[n][3] - mn1);
            rs0 += sf[n][0] + sf[n][1];
            rs1 += sf[n][2] + sf[n][3];
        }
        rs0 += __shfl_xor_sync(0xffffffffu, rs0, 1);
        rs0 += __shfl_xor_sync(0xffffffffu, rs0, 2);
        rs1 += __shfl_xor_sync(0xffffffffu, rs1, 1);
        rs1 += __shfl_xor_sync(0xffffffffu, rs1, 2);
        l0 = l0 * c0 + rs0;
        l1 = l1 * c1 + rs1;

        #pragma unroll
        for (int n = 0; n < 16; n++) {
            oacc[n][0] *= c0; oacc[n][1] *= c0;
            oacc[n][2] *= c1; oacc[n][3] *= c1;
        }

        // ---- P -> smem (A-frag layout roundtrip) ----
        __syncwarp();
        #pragma unroll
        for (int n = 0; n < 4; n++) {
            *(float2*)&Psm[lr]    [n * 8 + 2 * lc] =
                make_float2(to_tf32(sf[n][0]), to_tf32(sf[n][1]));
            *(float2*)&Psm[lr + 8][n * 8 + 2 * lc] =
                make_float2(to_tf32(sf[n][2]), to_tf32(sf[n][3]));
        }
        __syncwarp();

        // ---- O += P @ V[:, vh*128 .. +128] ----
        const int vb = vh * 128;
        #pragma unroll
        for (int ks = 0; ks < 4; ks++) {
            uint32_t af[4];
            af[0] = __float_as_uint(Psm[lr]    [ks * 8 + lc]);
            af[1] = __float_as_uint(Psm[lr + 8][ks * 8 + lc]);
            af[2] = __float_as_uint(Psm[lr]    [ks * 8 + lc + 4]);
            af[3] = __float_as_uint(Psm[lr + 8][ks * 8 + lc + 4]);
            #pragma unroll
            for (int n = 0; n < 16; n++) {
                uint32_t bf[2];
                bf[0] = __float_as_uint(Vs[ks * 8 + lc]    [vb + n * 8 + lr]);
                bf[1] = __float_as_uint(Vs[ks * 8 + lc + 4][vb + n * 8 + lr]);
                mma_tf32(oacc[n], af, bf);
            }
        }
    }

    // ---- epilogue: combine branches, GroupNorm ----
    __syncthreads();
    const int orow0 = rg * 16 + lr;
    const int vb = vh * 128;
    if (br == 0) {
        float r0 = 1.f / l0, r1 = 1.f / l1;
        #pragma unroll
        for (int n = 0; n < 16; n++) {
            *(float2*)&Osm[orow0]    [vb + n * 8 + 2 * lc] =
                make_float2(oacc[n][0] * r0, oacc[n][1] * r0);
            *(float2*)&Osm[orow0 + 8][vb + n * 8 + 2 * lc] =
                make_float2(oacc[n][2] * r1, oacc[n][3] * r1);
        }
    }
    __syncthreads();
    if (br == 1) {
        const float lam = g_lambda;
        float r0 = lam / l0, r1 = lam / l1;
        #pragma unroll
        for (int n = 0; n < 16; n++) {
            float2 a0 = *(float2*)&Osm[orow0]    [vb + n * 8 + 2 * lc];
            float2 a1 = *(float2*)&Osm[orow0 + 8][vb + n * 8 + 2 * lc];
            a0.x -= oacc[n][0] * r0; a0.y -= oacc[n][1] * r0;
            a1.x -= oacc[n][2] * r1; a1.y -= oacc[n][3] * r1;
            *(float2*)&Osm[orow0]    [vb + n * 8 + 2 * lc] = a0;
            *(float2*)&Osm[orow0 + 8][vb + n * 8 + 2 * lc] = a1;
        }
    }
    __syncthreads();

    // GroupNorm: warp w -> rows w*4..w*4+3
    const float4 gw0 = *(const float4*)&gnw[h * 256 + lane * 4];
    const float4 gw1 = *(const float4*)&gnw[h * 256 + 128 + lane * 4];
    const float4 gb0 = *(const float4*)&gnb[h * 256 + lane * 4];
    const float4 gb1 = *(const float4*)&gnb[h * 256 + 128 + lane * 4];
    #pragma unroll
    for (int i = 0; i < 4; i++) {
        int r = warp * 4 + i;
        float4 v0 = *(float4*)&Osm[r][lane * 4];
        float4 v1 = *(float4*)&Osm[r][128 + lane * 4];
        float sum = v0.x + v0.y + v0.z + v0.w + v1.x + v1.y + v1.z + v1.w;
        float ss  = v0.x*v0.x + v0.y*v0.y + v0.z*v0.z + v0.w*v0.w
                  + v1.x*v1.x + v1.y*v1.y + v1.z*v1.z + v1.w*v1.w;
        #pragma unroll
        for (int o = 16; o; o >>= 1) {
            sum += __shfl_xor_sync(0xffffffffu, sum, o);
            ss  += __shfl_xor_sync(0xffffffffu, ss, o);
        }
        float mean = sum * (1.f / 256.f);
        float var = ss * (1.f / 256.f) - mean * mean;
        float rstd = rsqrtf(var + GN_EPS_F);
        float4 o0, o1;
        o0.x = ((v0.x - mean) * rstd * gw0.x + gb0.x) * ONE_MINUS_LI_F;
        o0.y = ((v0.y - mean) * rstd * gw0.y + gb0.y) * ONE_MINUS_LI_F;
        o0.z = ((v0.z - mean) * rstd * gw0.z + gb0.z) * ONE_MINUS_LI_F;
        o0.w = ((v0.w - mean) * rstd * gw0.w + gb0.w) * ONE_MINUS_LI_F;
        o1.x = ((v1.x - mean) * rstd * gw1.x + gb1.x) * ONE_MINUS_LI_F;
        o1.y = ((v1.y - mean) * rstd * gw1.y + gb1.y) * ONE_MINUS_LI_F;
        o1.z = ((v1.z - mean) * rstd * gw1.z + gb1.z) * ONE_MINUS_LI_F;
        o1.w = ((v1.w - mean) * rstd * gw1.w + gb1.w) * ONE_MINUS_LI_F;
        size_t ob = (size_t)(b * T_ + q0 + r) * 4096 + h * 256;
        *(float4*)&O[ob + lane * 4]       = o0;
        *(float4*)&O[ob + 128 + lane * 4] = o1;
    }
}

// ---------------- host launcher -----------------------------------------------
extern "C" void kernel_launch(void* const* d_in, const int* in_sizes, int n_in,
                              void* d_out, int out_size) {
    const float* x   = (const float*)d_in[0];
    const float* Wq  = (const float*)d_in[1];
    const float* Wk  = (const float*)d_in[2];
    const float* Wv  = (const float*)d_in[3];
    const float* Wo  = (const float*)d_in[4];
    const float* lq1 = (const float*)d_in[5];
    const float* lk1 = (const float*)d_in[6];
    const float* lq2 = (const float*)d_in[7];
    const float* lk2 = (const float*)d_in[8];
    const float* gnw = (const float*)d_in[9];
    const float* gnb = (const float*)d_in[10];
    const int*   pos = (const int*)d_in[11];
    float* out = (float*)d_out;

    float *pQ, *pK, *pV, *pO;
    cudaGetSymbolAddress((void**)&pQ, g_Q);
    cudaGetSymbolAddress((void**)&pK, g_K);
    cudaGetSymbolAddress((void**)&pV, g_V);
    cudaGetSymbolAddress((void**)&pO, g_O);

    const int M = B_ * T_;   // 2048
    const int attn_smem = SM_TOTF * 4;  // 86016 B
    cudaFuncSetAttribute(attn_kernel, cudaFuncAttributeMaxDynamicSharedMemorySize, attn_smem);

    lambda_kernel<<<1, 32>>>(lq1, lk1, lq2, lk2);

    gemm_qkv<<<dim3(48, M / 128), 256>>>(x, Wq, Wk, Wv, pQ, pK, pV);

    {
        int npq = M * H_ * 2 * 64;
        int npk = M * KVH_ * 2 * 64;
        rope_kernel<<<(npq + 255) / 256, 256>>>(pQ, pos, 2 * H_, npq);
        rope_kernel<<<(npk + 255) / 256, 256>>>(pK, pos, 2 * KVH_, npk);
    }

    attn_kernel<<<dim3(T_ / 32, B_ * H_), 256, attn_smem>>>(pQ, pK, pV, pO, gnw, gnb);

    gemm_nt_db<<<dim3(D_ / 128, M / 128), 256>>>(pO, Wo, out, D_, 4096);
}

// round 5
// speedup vs baseline: 2.3287x; 1.0049x over previous
#include <cuda_runtime.h>
#include <math.h>
#include <stdint.h>

#define B_  2
#define T_  1024
#define D_  2048
#define H_  16
#define KVH_ 4
#define DH_ 128
#define REP_ 4

#define LAMBDA_INIT_F   0.35550906759096927f
#define ONE_MINUS_LI_F  0.64449093240903073f
#define GN_EPS_F        1e-5f
#define SCALE_F         0.08838834764831845f  // 1/sqrt(128)

// GEMM pipeline config: BK=8, 4 stages, pad to 12 floats/row (conflict-free)
#define PADK8 12
#define GEMM_SMEM_BYTES (4 * 128 * PADK8 * 2 * 4)   // 49152

// ---------------- scratch ----------------------------------------------------
static __device__ float g_Q[(size_t)B_*T_*H_*2*DH_];    // (2048, 4096)
static __device__ float g_K[(size_t)B_*T_*KVH_*2*DH_];  // (2048, 1024)
static __device__ float g_V[(size_t)B_*T_*KVH_*2*DH_];  // (2048, 1024)
static __device__ float g_O[(size_t)B_*T_*H_*2*DH_];    // (2048, 4096)
static __device__ float g_lambda;

// ---------------- helpers ----------------------------------------------------
__device__ __forceinline__ float to_tf32(float x) {
    float r;
    asm("cvt.rna.tf32.f32 %0, %1;" : "=f"(r) : "f"(x));
    return r;
}
__device__ __forceinline__ float4 to_tf32_4(float4 v) {
    v.x = to_tf32(v.x); v.y = to_tf32(v.y);
    v.z = to_tf32(v.z); v.w = to_tf32(v.w);
    return v;
}
__device__ __forceinline__ uint32_t tf32_bits(float x) {
    float r;
    asm("cvt.rna.tf32.f32 %0, %1;" : "=f"(r) : "f"(x));
    return __float_as_uint(r);
}
__device__ __forceinline__ void mma_tf32(float* c, const uint32_t* a, const uint32_t* b) {
    asm volatile(
        "mma.sync.aligned.m16n8k8.row.col.f32.tf32.tf32.f32 "
        "{%0,%1,%2,%3}, {%4,%5,%6,%7}, {%8,%9}, {%0,%1,%2,%3};"
        : "+f"(c[0]), "+f"(c[1]), "+f"(c[2]), "+f"(c[3])
        : "r"(a[0]), "r"(a[1]), "r"(a[2]), "r"(a[3]), "r"(b[0]), "r"(b[1]));
}
__device__ __forceinline__ void cp_async16(uint32_t smem_dst, const void* gsrc) {
    asm volatile("cp.async.cg.shared.global [%0], [%1], 16;" :: "r"(smem_dst), "l"(gsrc));
}
__device__ __forceinline__ void cp_commit() {
    asm volatile("cp.async.commit_group;" ::: "memory");
}
template <int N>
__device__ __forceinline__ void cp_wait() {
    asm volatile("cp.async.wait_group %0;" :: "n"(N) : "memory");
}

// ---------------- lambda scalar ----------------------------------------------
__global__ void lambda_kernel(const float* __restrict__ lq1, const float* __restrict__ lk1,
                              const float* __restrict__ lq2, const float* __restrict__ lk2) {
    int lane = threadIdx.x;
    float d1 = 0.f, d2 = 0.f;
    #pragma unroll
    for (int i = 0; i < 4; i++) {
        int idx = lane * 4 + i;
        d1 += lq1[idx] * lk1[idx];
        d2 += lq2[idx] * lk2[idx];
    }
    #pragma unroll
    for (int o = 16; o; o >>= 1) {
        d1 += __shfl_xor_sync(0xffffffffu, d1, o);
        d2 += __shfl_xor_sync(0xffffffffu, d2, o);
    }
    if (lane == 0)
        g_lambda = expf(d1) - expf(d2) + LAMBDA_INIT_F;
}

// ---------------- cp.async 4-stage tf32 GEMM body ----------------------------
// C[128,128] = A[128,K] @ W[128,K]^T. 256 thr = 8 warps (2M x 4N), warp 64x32.
// BK=8, 4 smem stages, 1 syncthreads per k-tile.
__device__ __forceinline__ void gemm_body(
    const float* __restrict__ Ablk, const float* __restrict__ Bblk,
    float* __restrict__ Cblk, int K, int ldc, float* smem)
{
    float (*As)[128][PADK8] = (float(*)[128][PADK8])smem;
    float (*Bs)[128][PADK8] = (float(*)[128][PADK8])(smem + 4 * 128 * PADK8);

    const int tid  = threadIdx.x;
    const int warp = tid >> 5;
    const int lane = tid & 31;
    const int wm = (warp >> 2) * 64;
    const int wn = (warp & 3) * 32;
    const int lr = lane >> 2;
    const int lc = lane & 3;

    // loader: each thread copies one 16B chunk of A and one of B per tile
    const int l_row = tid >> 1;          // 0..127
    const int l_col = (tid & 1) * 4;     // 0 or 4
    const float* Ag = Ablk + (size_t)l_row * K + l_col;
    const float* Bg = Bblk + (size_t)l_row * K + l_col;

    uint32_t a_dst[4], b_dst[4];
    #pragma unroll
    for (int s = 0; s < 4; s++) {
        a_dst[s] = (uint32_t)__cvta_generic_to_shared(&As[s][l_row][l_col]);
        b_dst[s] = (uint32_t)__cvta_generic_to_shared(&Bs[s][l_row][l_col]);
    }

    float acc[4][4][4];
    #pragma unroll
    for (int mi = 0; mi < 4; mi++)
        #pragma unroll
        for (int ni = 0; ni < 4; ni++)
            #pragma unroll
            for (int r = 0; r < 4; r++)
                acc[mi][ni][r] = 0.f;

    const int nt = K / 8;

    // prologue: stages 0..2
    #pragma unroll
    for (int p = 0; p < 3; p++) {
        cp_async16(a_dst[p], Ag + (size_t)p * 8);
        cp_async16(b_dst[p], Bg + (size_t)p * 8);
        cp_commit();
    }

    for (int t = 0; t < nt; t++) {
        cp_wait<2>();
        __syncthreads();
        const int s = t & 3;

        uint32_t af[4][4], bf[4][2];
        #pragma unroll
        for (int mi = 0; mi < 4; mi++) {
            af[mi][0] = tf32_bits(As[s][wm + mi * 16 + lr]    [lc]);
            af[mi][1] = tf32_bits(As[s][wm + mi * 16 + lr + 8][lc]);
            af[mi][2] = tf32_bits(As[s][wm + mi * 16 + lr]    [lc + 4]);
            af[mi][3] = tf32_bits(As[s][wm + mi * 16 + lr + 8][lc + 4]);
        }
        #pragma unroll
        for (int ni = 0; ni < 4; ni++) {
            bf[ni][0] = tf32_bits(Bs[s][wn + ni * 8 + lr][lc]);
            bf[ni][1] = tf32_bits(Bs[s][wn + ni * 8 + lr][lc + 4]);
        }
        #pragma unroll
        for (int mi = 0; mi < 4; mi++)
            #pragma unroll
            for (int ni = 0; ni < 4; ni++)
                mma_tf32(acc[mi][ni], af[mi], bf[ni]);

        if (t + 3 < nt) {
            const int sn = (t + 3) & 3;
            cp_async16(a_dst[sn], Ag + (size_t)(t + 3) * 8);
            cp_async16(b_dst[sn], Bg + (size_t)(t + 3) * 8);
        }
        cp_commit();
    }

    #pragma unroll
    for (int mi = 0; mi < 4; mi++) {
        #pragma unroll
        for (int ni = 0; ni < 4; ni++) {
            int r0 = wm + mi * 16 + lr;
            int cc = wn + ni * 8 + 2 * lc;
            *(float2*)&Cblk[(size_t)r0 * ldc + cc] =
                make_float2(acc[mi][ni][0], acc[mi][ni][1]);
            *(float2*)&Cblk[(size_t)(r0 + 8) * ldc + cc] =
                make_float2(acc[mi][ni][2], acc[mi][ni][3]);
        }
    }
}

// ---------------- fused QKV projection ----------------------------------------
__global__ void __launch_bounds__(256, 2) gemm_qkv(const float* __restrict__ x,
                                                   const float* __restrict__ Wq,
                                                   const float* __restrict__ Wk,
                                                   const float* __restrict__ Wv,
                                                   float* __restrict__ Q,
                                                   float* __restrict__ K,
                                                   float* __restrict__ V) {
    extern __shared__ float smem[];
    const int bx = blockIdx.x;
    const int bm = blockIdx.y * 128;
    const float* W; float* C; int ldc, bn;
    if (bx < 32)      { W = Wq; C = Q; ldc = 4096; bn = bx * 128; }
    else if (bx < 40) { W = Wk; C = K; ldc = 1024; bn = (bx - 32) * 128; }
    else              { W = Wv; C = V; ldc = 1024; bn = (bx - 40) * 128; }
    gemm_body(x + (size_t)bm * D_, W + (size_t)bn * D_,
              C + (size_t)bm * ldc + bn, D_, ldc, smem);
}

// ---------------- generic GEMM (output projection) ----------------------------
__global__ void __launch_bounds__(256, 2) gemm_nt_db(const float* __restrict__ A,
                                                     const float* __restrict__ W,
                                                     float* __restrict__ C,
                                                     int N, int K) {
    extern __shared__ float smem[];
    const int bm = blockIdx.y * 128;
    const int bn = blockIdx.x * 128;
    gemm_body(A + (size_t)bm * K, W + (size_t)bn * K,
              C + (size_t)bm * N + bn, K, N, smem);
}

// ---------------- RoPE (in place) ---------------------------------------------
__global__ void rope_kernel(float* __restrict__ X, const int* __restrict__ pos,
                            int nheads2, int npairs_total) {
    int idx = blockIdx.x * blockDim.x + threadIdx.x;
    if (idx >= npairs_total) return;
    int i = idx & 63;
    int row = idx >> 6;
    int t = (row / nheads2) % T_;
    float inv = exp2f((float)i * (-13.287712379549449f / 64.0f));
    float ang = (float)pos[t] * inv;
    float s, c;
    sincosf(ang, &s, &c);
    float* p = X + (size_t)row * 128 + 2 * i;
    float x1 = p[0], x2 = p[1];
    p[0] = x1 * c - x2 * s;
    p[1] = x1 * s + x2 * c;
}

// ---------------- tensor-core dual flash attention + diff + GroupNorm ---------
#define SM_K1 0
#define SM_K2 4224
#define SM_V  8448
#define SM_P  16896
#define SM_TOTF 21504

__global__ void __launch_bounds__(256) attn_kernel(const float* __restrict__ Q,
                                                   const float* __restrict__ Kg,
                                                   const float* __restrict__ Vg,
                                                   float* __restrict__ O,
                                                   const float* __restrict__ gnw,
                                                   const float* __restrict__ gnb) {
    extern __shared__ float smem[];
    float (*K1s)[132] = (float(*)[132])(smem + SM_K1);
    float (*K2s)[132] = (float(*)[132])(smem + SM_K2);
    float (*Vs)[264]  = (float(*)[264])(smem + SM_V);
    float (*QS)[260]  = (float(*)[260])smem;
    float (*Osm)[264] = (float(*)[264])smem;

    const int tid  = threadIdx.x;
    const int warp = tid >> 5;
    const int lane = tid & 31;
    const int lr = lane >> 2;
    const int lc = lane & 3;
    const int br = warp >> 2;
    const int rg = (warp >> 1) & 1;
    const int vh = warp & 1;

    float (*Psm)[36] = (float(*)[36])(smem + SM_P + warp * 576);

    const int bh = blockIdx.y;
    const int b = bh / H_;
    const int h = bh % H_;
    const int kvh = h / REP_;
    const int q0 = blockIdx.x * 32;

    #pragma unroll
    for (int r = 0; r < 8; r++) {
        int idx = tid + 256 * r;
        int qr = idx >> 6;
        int c4 = (idx & 63) * 4;
        float4 v = *(const float4*)&Q[((size_t)(b * T_ + q0 + qr) * H_ + h) * 256 + c4];
        v.x *= SCALE_F; v.y *= SCALE_F; v.z *= SCALE_F; v.w *= SCALE_F;
        *(float4*)&QS[qr][c4] = to_tf32_4(v);
    }
    __syncthreads();

    uint32_t qf[16][4];
    {
        const int r0 = rg * 16 + lr;
        const int cb = br * 128;
        #pragma unroll
        for (int ks = 0; ks < 16; ks++) {
            qf[ks][0] = __float_as_uint(QS[r0]    [cb + ks * 8 + lc]);
            qf[ks][1] = __float_as_uint(QS[r0 + 8][cb + ks * 8 + lc]);
            qf[ks][2] = __float_as_uint(QS[r0]    [cb + ks * 8 + lc + 4]);
            qf[ks][3] = __float_as_uint(QS[r0 + 8][cb + ks * 8 + lc + 4]);
        }
    }

    float oacc[16][4];
    #pragma unroll
    for (int n = 0; n < 16; n++)
        #pragma unroll
        for (int r = 0; r < 4; r++)
            oacc[n][r] = 0.f;
    float m0 = -1e30f, m1 = -1e30f, l0 = 0.f, l1 = 0.f;

    const float (*Ks)[132] = br ? K2s : K1s;
    const int row0 = q0 + rg * 16 + lr;
    const int row1 = row0 + 8;
    const int ntiles = q0 / 32 + 1;

    for (int kt = 0; kt < ntiles; kt++) {
        const int k0 = kt * 32;
        __syncthreads();
        #pragma unroll
        for (int r = 0; r < 8; r++) {
            int idx = tid + 256 * r;
            int j = idx >> 6;
            int c4 = idx & 63;
            size_t kb = ((size_t)(b * T_ + k0 + j) * KVH_ + kvh) * 256;
            float4 kv = to_tf32_4(*(const float4*)&Kg[kb + c4 * 4]);
            if (c4 < 32) *(float4*)&K1s[j][c4 * 4] = kv;
            else         *(float4*)&K2s[j][(c4 - 32) * 4] = kv;
            float4 vv = to_tf32_4(*(const float4*)&Vg[kb + c4 * 4]);
            *(float4*)&Vs[j][c4 * 4] = vv;
        }
        __syncthreads();

        float sf[4][4];
        #pragma unroll
        for (int n = 0; n < 4; n++)
            #pragma unroll
            for (int r = 0; r < 4; r++)
                sf[n][r] = 0.f;
        #pragma unroll
        for (int n = 0; n < 4; n++) {
            #pragma unroll
            for (int ks = 0; ks < 16; ks++) {
                uint32_t bf[2];
                bf[0] = __float_as_uint(Ks[n * 8 + lr][ks * 8 + lc]);
                bf[1] = __float_as_uint(Ks[n * 8 + lr][ks * 8 + lc + 4]);
                mma_tf32(sf[n], qf[ks], bf);
            }
        }

        if (kt == ntiles - 1) {
            #pragma unroll
            for (int n = 0; n < 4; n++) {
                int key = k0 + n * 8 + 2 * lc;
                if (key     > row0) sf[n][0] = -1e30f;
                if (key + 1 > row0) sf[n][1] = -1e30f;
                if (key     > row1) sf[n][2] = -1e30f;
                if (key + 1 > row1) sf[n][3] = -1e30f;
            }
        }

        float mx0 = -1e30f, mx1 = -1e30f;
        #pragma unroll
        for (int n = 0; n < 4; n++) {
            mx0 = fmaxf(mx0, fmaxf(sf[n][0], sf[n][1]));
            mx1 = fmaxf(mx1, fmaxf(sf[n][2], sf[n][3]));
        }
        mx0 = fmaxf(mx0, __shfl_xor_sync(0xffffffffu, mx0, 1));
        mx0 = fmaxf(mx0, __shfl_xor_sync(0xffffffffu, mx0, 2));
        mx1 = fmaxf(mx1, __shfl_xor_sync(0xffffffffu, mx1, 1));
        mx1 = fmaxf(mx1, __shfl_xor_sync(0xffffffffu, mx1, 2));

        float mn0 = fmaxf(m0, mx0), mn1 = fmaxf(m1, mx1);
        float c0 = __expf(m0 - mn0), c1 = __expf(m1 - mn1);
        m0 = mn0; m1 = mn1;

        float rs0 = 0.f, rs1 = 0.f;
        #pragma unroll
        for (int n = 0; n < 4; n++) {
            sf[n][0] = __expf(sf[n][0] - mn0);
            sf[n][1] = __expf(sf[n][1] - mn0);
            sf[n][2] = __expf(sf[n][2] - mn1);
            sf[n][3] = __expf(sf[n][3] - mn1);
            rs0 += sf[n][0] + sf[n][1];
            rs1 += sf[n][2] + sf[n][3];
        }
        rs0 += __shfl_xor_sync(0xffffffffu, rs0, 1);
        rs0 += __shfl_xor_sync(0xffffffffu, rs0, 2);
        rs1 += __shfl_xor_sync(0xffffffffu, rs1, 1);
        rs1 += __shfl_xor_sync(0xffffffffu, rs1, 2);
        l0 = l0 * c0 + rs0;
        l1 = l1 * c1 + rs1;

        #pragma unroll
        for (int n = 0; n < 16; n++) {
            oacc[n][0] *= c0; oacc[n][1] *= c0;
            oacc[n][2] *= c1; oacc[n][3] *= c1;
        }

        __syncwarp();
        #pragma unroll
        for (int n = 0; n < 4; n++) {
            *(float2*)&Psm[lr]    [n * 8 + 2 * lc] =
                make_float2(to_tf32(sf[n][0]), to_tf32(sf[n][1]));
            *(float2*)&Psm[lr + 8][n * 8 + 2 * lc] =
                make_float2(to_tf32(sf[n][2]), to_tf32(sf[n][3]));
        }
        __syncwarp();

        const int vb = vh * 128;
        #pragma unroll
        for (int ks = 0; ks < 4; ks++) {
            uint32_t af[4];
            af[0] = __float_as_uint(Psm[lr]    [ks * 8 + lc]);
            af[1] = __float_as_uint(Psm[lr + 8][ks * 8 + lc]);
            af[2] = __float_as_uint(Psm[lr]    [ks * 8 + lc + 4]);
            af[3] = __float_as_uint(Psm[lr + 8][ks * 8 + lc + 4]);
            #pragma unroll
            for (int n = 0; n < 16; n++) {
                uint32_t bf[2];
                bf[0] = __float_as_uint(Vs[ks * 8 + lc]    [vb + n * 8 + lr]);
                bf[1] = __float_as_uint(Vs[ks * 8 + lc + 4][vb + n * 8 + lr]);
                mma_tf32(oacc[n], af, bf);
            }
        }
    }

    __syncthreads();
    const int orow0 = rg * 16 + lr;
    const int vb = vh * 128;
    if (br == 0) {
        float r0 = 1.f / l0, r1 = 1.f / l1;
        #pragma unroll
        for (int n = 0; n < 16; n++) {
            *(float2*)&Osm[orow0]    [vb + n * 8 + 2 * lc] =
                make_float2(oacc[n][0] * r0, oacc[n][1] * r0);
            *(float2*)&Osm[orow0 + 8][vb + n * 8 + 2 * lc] =
                make_float2(oacc[n][2] * r1, oacc[n][3] * r1);
        }
    }
    __syncthreads();
    if (br == 1) {
        const float lam = g_lambda;
        float r0 = lam / l0, r1 = lam / l1;
        #pragma unroll
        for (int n = 0; n < 16; n++) {
            float2 a0 = *(float2*)&Osm[orow0]    [vb + n * 8 + 2 * lc];
            float2 a1 = *(float2*)&Osm[orow0 + 8][vb + n * 8 + 2 * lc];
            a0.x -= oacc[n][0] * r0; a0.y -= oacc[n][1] * r0;
            a1.x -= oacc[n][2] * r1; a1.y -= oacc[n][3] * r1;
            *(float2*)&Osm[orow0]    [vb + n * 8 + 2 * lc] = a0;
            *(float2*)&Osm[orow0 + 8][vb + n * 8 + 2 * lc] = a1;
        }
    }
    __syncthreads();

    const float4 gw0 = *(const float4*)&gnw[h * 256 + lane * 4];
    const float4 gw1 = *(const float4*)&gnw[h * 256 + 128 + lane * 4];
    const float4 gb0 = *(const float4*)&gnb[h * 256 + lane * 4];
    const float4 gb1 = *(const float4*)&gnb[h * 256 + 128 + lane * 4];
    #pragma unroll
    for (int i = 0; i < 4; i++) {
        int r = warp * 4 + i;
        float4 v0 = *(float4*)&Osm[r][lane * 4];
        float4 v1 = *(float4*)&Osm[r][128 + lane * 4];
        float sum = v0.x + v0.y + v0.z + v0.w + v1.x + v1.y + v1.z + v1.w;
        float ss  = v0.x*v0.x + v0.y*v0.y + v0.z*v0.z + v0.w*v0.w
                  + v1.x*v1.x + v1.y*v1.y + v1.z*v1.z + v1.w*v1.w;
        #pragma unroll
        for (int o = 16; o; o >>= 1) {
            sum += __shfl_xor_sync(0xffffffffu, sum, o);
            ss  += __shfl_xor_sync(0xffffffffu, ss, o);
        }
        float mean = sum * (1.f / 256.f);
        float var = ss * (1.f / 256.f) - mean * mean;
        float rstd = rsqrtf(var + GN_EPS_F);
        float4 o0, o1;
        o0.x = ((v0.x - mean) * rstd * gw0.x + gb0.x) * ONE_MINUS_LI_F;
        o0.y = ((v0.y - mean) * rstd * gw0.y + gb0.y) * ONE_MINUS_LI_F;
        o0.z = ((v0.z - mean) * rstd * gw0.z + gb0.z) * ONE_MINUS_LI_F;
        o0.w = ((v0.w - mean) * rstd * gw0.w + gb0.w) * ONE_MINUS_LI_F;
        o1.x = ((v1.x - mean) * rstd * gw1.x + gb1.x) * ONE_MINUS_LI_F;
        o1.y = ((v1.y - mean) * rstd * gw1.y + gb1.y) * ONE_MINUS_LI_F;
        o1.z = ((v1.z - mean) * rstd * gw1.z + gb1.z) * ONE_MINUS_LI_F;
        o1.w = ((v1.w - mean) * rstd * gw1.w + gb1.w) * ONE_MINUS_LI_F;
        size_t ob = (size_t)(b * T_ + q0 + r) * 4096 + h * 256;
        *(float4*)&O[ob + lane * 4]       = o0;
        *(float4*)&O[ob + 128 + lane * 4] = o1;
    }
}

// ---------------- host launcher -----------------------------------------------
extern "C" void kernel_launch(void* const* d_in, const int* in_sizes, int n_in,
                              void* d_out, int out_size) {
    const float* x   = (const float*)d_in[0];
    const float* Wq  = (const float*)d_in[1];
    const float* Wk  = (const float*)d_in[2];
    const float* Wv  = (const float*)d_in[3];
    const float* Wo  = (const float*)d_in[4];
    const float* lq1 = (const float*)d_in[5];
    const float* lk1 = (const float*)d_in[6];
    const float* lq2 = (const float*)d_in[7];
    const float* lk2 = (const float*)d_in[8];
    const float* gnw = (const float*)d_in[9];
    const float* gnb = (const float*)d_in[10];
    const int*   pos = (const int*)d_in[11];
    float* out = (float*)d_out;

    float *pQ, *pK, *pV, *pO;
    cudaGetSymbolAddress((void**)&pQ, g_Q);
    cudaGetSymbolAddress((void**)&pK, g_K);
    cudaGetSymbolAddress((void**)&pV, g_V);
    cudaGetSymbolAddress((void**)&pO, g_O);

    const int M = B_ * T_;   // 2048
    const int attn_smem = SM_TOTF * 4;  // 86016 B
    cudaFuncSetAttribute(attn_kernel, cudaFuncAttributeMaxDynamicSharedMemorySize, attn_smem);
    cudaFuncSetAttribute(gemm_qkv, cudaFuncAttributeMaxDynamicSharedMemorySize, GEMM_SMEM_BYTES);
    cudaFuncSetAttribute(gemm_nt_db, cudaFuncAttributeMaxDynamicSharedMemorySize, GEMM_SMEM_BYTES);

    lambda_kernel<<<1, 32>>>(lq1, lk1, lq2, lk2);

    gemm_qkv<<<dim3(48, M / 128), 256, GEMM_SMEM_BYTES>>>(x, Wq, Wk, Wv, pQ, pK, pV);

    {
        int npq = M * H_ * 2 * 64;
        int npk = M * KVH_ * 2 * 64;
        rope_kernel<<<(npq + 255) / 256, 256>>>(pQ, pos, 2 * H_, npq);
        rope_kernel<<<(npk + 255) / 256, 256>>>(pK, pos, 2 * KVH_, npk);
    }

    attn_kernel<<<dim3(T_ / 32, B_ * H_), 256, attn_smem>>>(pQ, pK, pV, pO, gnw, gnb);

    gemm_nt_db<<<dim3(D_ / 128, M / 128), 256, GEMM_SMEM_BYTES>>>(pO, Wo, out, D_, 4096);
}

// round 6
// speedup vs baseline: 3.2393x; 1.3910x over previous
#include <cuda_runtime.h>
#include <cuda_fp16.h>
#include <math.h>
#include <stdint.h>

#define B_  2
#define T_  1024
#define D_  2048
#define H_  16
#define KVH_ 4
#define DH_ 128
#define REP_ 4

#define LAMBDA_INIT_F   0.35550906759096927f
#define ONE_MINUS_LI_F  0.64449093240903073f
#define GN_EPS_F        1e-5f
#define SCALE_F         0.08838834764831845f  // 1/sqrt(128)

// fp16 GEMM pipeline: BK=16, 4 stages, row stride 24 halves (conflict-free)
#define BKH  16
#define LDH  24
#define GEMM_SMEM_BYTES (4 * 128 * LDH * 2 * 2)   // 49152 B

// ---------------- scratch ----------------------------------------------------
static __device__ float  g_Q[(size_t)B_*T_*H_*2*DH_];    // (2048, 4096) fp32
static __device__ float  g_K[(size_t)B_*T_*KVH_*2*DH_];  // (2048, 1024) fp32
static __device__ float  g_V[(size_t)B_*T_*KVH_*2*DH_];  // (2048, 1024) fp32
static __device__ __half g_Xh[(size_t)B_*T_*D_];         // x in fp16
static __device__ __half g_Wqh[(size_t)2*H_*DH_*D_];
static __device__ __half g_Wkh[(size_t)2*KVH_*DH_*D_];
static __device__ __half g_Wvh[(size_t)2*KVH_*DH_*D_];
static __device__ __half g_Woh[(size_t)D_*2*H_*DH_];
static __device__ __half g_Oh[(size_t)B_*T_*H_*2*DH_];   // attn output fp16
static __device__ float  g_lambda;

// ---------------- helpers ----------------------------------------------------
__device__ __forceinline__ float to_tf32(float x) {
    float r;
    asm("cvt.rna.tf32.f32 %0, %1;" : "=f"(r) : "f"(x));
    return r;
}
__device__ __forceinline__ float4 to_tf32_4(float4 v) {
    v.x = to_tf32(v.x); v.y = to_tf32(v.y);
    v.z = to_tf32(v.z); v.w = to_tf32(v.w);
    return v;
}
__device__ __forceinline__ void mma_tf32(float* c, const uint32_t* a, const uint32_t* b) {
    asm volatile(
        "mma.sync.aligned.m16n8k8.row.col.f32.tf32.tf32.f32 "
        "{%0,%1,%2,%3}, {%4,%5,%6,%7}, {%8,%9}, {%0,%1,%2,%3};"
        : "+f"(c[0]), "+f"(c[1]), "+f"(c[2]), "+f"(c[3])
        : "r"(a[0]), "r"(a[1]), "r"(a[2]), "r"(a[3]), "r"(b[0]), "r"(b[1]));
}
__device__ __forceinline__ void mma_f16(float* c, const uint32_t* a, const uint32_t* b) {
    asm volatile(
        "mma.sync.aligned.m16n8k16.row.col.f32.f16.f16.f32 "
        "{%0,%1,%2,%3}, {%4,%5,%6,%7}, {%8,%9}, {%0,%1,%2,%3};"
        : "+f"(c[0]), "+f"(c[1]), "+f"(c[2]), "+f"(c[3])
        : "r"(a[0]), "r"(a[1]), "r"(a[2]), "r"(a[3]), "r"(b[0]), "r"(b[1]));
}
__device__ __forceinline__ void cp_async16(uint32_t smem_dst, const void* gsrc) {
    asm volatile("cp.async.cg.shared.global [%0], [%1], 16;" :: "r"(smem_dst), "l"(gsrc));
}
__device__ __forceinline__ void cp_commit() {
    asm volatile("cp.async.commit_group;" ::: "memory");
}
template <int N>
__device__ __forceinline__ void cp_wait() {
    asm volatile("cp.async.wait_group %0;" :: "n"(N) : "memory");
}

// ---------------- fp32 -> fp16 convert ----------------------------------------
__global__ void f2h_kernel(const float* __restrict__ src, __half* __restrict__ dst, int n4) {
    int i = blockIdx.x * blockDim.x + threadIdx.x;
    if (i >= n4) return;
    float4 v = ((const float4*)src)[i];
    __half2 h0 = __floats2half2_rn(v.x, v.y);
    __half2 h1 = __floats2half2_rn(v.z, v.w);
    ((__half2*)dst)[2 * i]     = h0;
    ((__half2*)dst)[2 * i + 1] = h1;
}

// ---------------- lambda scalar ----------------------------------------------
__global__ void lambda_kernel(const float* __restrict__ lq1, const float* __restrict__ lk1,
                              const float* __restrict__ lq2, const float* __restrict__ lk2) {
    int lane = threadIdx.x;
    float d1 = 0.f, d2 = 0.f;
    #pragma unroll
    for (int i = 0; i < 4; i++) {
        int idx = lane * 4 + i;
        d1 += lq1[idx] * lk1[idx];
        d2 += lq2[idx] * lk2[idx];
    }
    #pragma unroll
    for (int o = 16; o; o >>= 1) {
        d1 += __shfl_xor_sync(0xffffffffu, d1, o);
        d2 += __shfl_xor_sync(0xffffffffu, d2, o);
    }
    if (lane == 0)
        g_lambda = expf(d1) - expf(d2) + LAMBDA_INIT_F;
}

// ---------------- fp16 m16n8k16 GEMM body (4-stage cp.async) ------------------
// C[128,128] = A[128,K] @ W[128,K]^T, fp16 in / fp32 out. 8 warps (2M x 4N).
__device__ __forceinline__ void gemm_body_h(
    const __half* __restrict__ Ablk, const __half* __restrict__ Bblk,
    float* __restrict__ Cblk, int K, int ldc, __half* smem)
{
    __half (*As)[128][LDH] = (__half(*)[128][LDH])smem;
    __half (*Bs)[128][LDH] = (__half(*)[128][LDH])(smem + 4 * 128 * LDH);

    const int tid  = threadIdx.x;
    const int warp = tid >> 5;
    const int lane = tid & 31;
    const int wm = (warp >> 2) * 64;
    const int wn = (warp & 3) * 32;
    const int lr = lane >> 2;
    const int lc = lane & 3;

    // loader: 128 rows x 16 halves = 256 chunks of 16B; 1 chunk per thread per array
    const int l_row = tid >> 1;
    const int l_ch  = (tid & 1) * 8;
    const __half* Ag = Ablk + (size_t)l_row * K + l_ch;
    const __half* Bg = Bblk + (size_t)l_row * K + l_ch;

    uint32_t a_dst[4], b_dst[4];
    #pragma unroll
    for (int s = 0; s < 4; s++) {
        a_dst[s] = (uint32_t)__cvta_generic_to_shared(&As[s][l_row][l_ch]);
        b_dst[s] = (uint32_t)__cvta_generic_to_shared(&Bs[s][l_row][l_ch]);
    }

    float acc[4][4][4];
    #pragma unroll
    for (int mi = 0; mi < 4; mi++)
        #pragma unroll
        for (int ni = 0; ni < 4; ni++)
            #pragma unroll
            for (int r = 0; r < 4; r++)
                acc[mi][ni][r] = 0.f;

    const int nt = K / BKH;

    #pragma unroll
    for (int p = 0; p < 3; p++) {
        cp_async16(a_dst[p], Ag + (size_t)p * BKH);
        cp_async16(b_dst[p], Bg + (size_t)p * BKH);
        cp_commit();
    }

    for (int t = 0; t < nt; t++) {
        cp_wait<2>();
        __syncthreads();
        const int s = t & 3;

        uint32_t af[4][4], bf[4][2];
        #pragma unroll
        for (int mi = 0; mi < 4; mi++) {
            af[mi][0] = *(const uint32_t*)&As[s][wm + mi * 16 + lr]    [2 * lc];
            af[mi][1] = *(const uint32_t*)&As[s][wm + mi * 16 + lr + 8][2 * lc];
            af[mi][2] = *(const uint32_t*)&As[s][wm + mi * 16 + lr]    [2 * lc + 8];
            af[mi][3] = *(const uint32_t*)&As[s][wm + mi * 16 + lr + 8][2 * lc + 8];
        }
        #pragma unroll
        for (int ni = 0; ni < 4; ni++) {
            bf[ni][0] = *(const uint32_t*)&Bs[s][wn + ni * 8 + lr][2 * lc];
            bf[ni][1] = *(const uint32_t*)&Bs[s][wn + ni * 8 + lr][2 * lc + 8];
        }
        #pragma unroll
        for (int mi = 0; mi < 4; mi++)
            #pragma unroll
            for (int ni = 0; ni < 4; ni++)
                mma_f16(acc[mi][ni], af[mi], bf[ni]);

        if (t + 3 < nt) {
            const int sn = (t + 3) & 3;
            cp_async16(a_dst[sn], Ag + (size_t)(t + 3) * BKH);
            cp_async16(b_dst[sn], Bg + (size_t)(t + 3) * BKH);
        }
        cp_commit();
    }

    #pragma unroll
    for (int mi = 0; mi < 4; mi++) {
        #pragma unroll
        for (int ni = 0; ni < 4; ni++) {
            int r0 = wm + mi * 16 + lr;
            int cc = wn + ni * 8 + 2 * lc;
            *(float2*)&Cblk[(size_t)r0 * ldc + cc] =
                make_float2(acc[mi][ni][0], acc[mi][ni][1]);
            *(float2*)&Cblk[(size_t)(r0 + 8) * ldc + cc] =
                make_float2(acc[mi][ni][2], acc[mi][ni][3]);
        }
    }
}

// ---------------- fused QKV projection -----------------------------------------
__global__ void __launch_bounds__(256, 2) gemm_qkv_h(const __half* __restrict__ x,
                                                     const __half* __restrict__ Wq,
                                                     const __half* __restrict__ Wk,
                                                     const __half* __restrict__ Wv,
                                                     float* __restrict__ Q,
                                                     float* __restrict__ K,
                                                     float* __restrict__ V) {
    extern __shared__ __half hsmem[];
    const int bx = blockIdx.x;
    const int bm = blockIdx.y * 128;
    const __half* W; float* C; int ldc, bn;
    if (bx < 32)      { W = Wq; C = Q; ldc = 4096; bn = bx * 128; }
    else if (bx < 40) { W = Wk; C = K; ldc = 1024; bn = (bx - 32) * 128; }
    else              { W = Wv; C = V; ldc = 1024; bn = (bx - 40) * 128; }
    gemm_body_h(x + (size_t)bm * D_, W + (size_t)bn * D_,
                C + (size_t)bm * ldc + bn, D_, ldc, hsmem);
}

// ---------------- output projection ---------------------------------------------
__global__ void __launch_bounds__(256, 2) gemm_out_h(const __half* __restrict__ A,
                                                     const __half* __restrict__ W,
                                                     float* __restrict__ C,
                                                     int N, int K) {
    extern __shared__ __half hsmem[];
    const int bm = blockIdx.y * 128;
    const int bn = blockIdx.x * 128;
    gemm_body_h(A + (size_t)bm * K, W + (size_t)bn * K,
                C + (size_t)bm * N + bn, K, N, hsmem);
}

// ---------------- RoPE (in place) ---------------------------------------------
__global__ void rope_kernel(float* __restrict__ X, const int* __restrict__ pos,
                            int nheads2, int npairs_total) {
    int idx = blockIdx.x * blockDim.x + threadIdx.x;
    if (idx >= npairs_total) return;
    int i = idx & 63;
    int row = idx >> 6;
    int t = (row / nheads2) % T_;
    float inv = exp2f((float)i * (-13.287712379549449f / 64.0f));
    float ang = (float)pos[t] * inv;
    float s, c;
    sincosf(ang, &s, &c);
    float* p = X + (size_t)row * 128 + 2 * i;
    float x1 = p[0], x2 = p[1];
    p[0] = x1 * c - x2 * s;
    p[1] = x1 * s + x2 * c;
}

// ---------------- tensor-core dual flash attention + diff + GroupNorm ---------
#define SM_K1 0
#define SM_K2 4224
#define SM_V  8448
#define SM_P  16896
#define SM_TOTF 21504

__global__ void __launch_bounds__(256) attn_kernel(const float* __restrict__ Q,
                                                   const float* __restrict__ Kg,
                                                   const float* __restrict__ Vg,
                                                   __half* __restrict__ Oh,
                                                   const float* __restrict__ gnw,
                                                   const float* __restrict__ gnb) {
    extern __shared__ float smem[];
    float (*K1s)[132] = (float(*)[132])(smem + SM_K1);
    float (*K2s)[132] = (float(*)[132])(smem + SM_K2);
    float (*Vs)[264]  = (float(*)[264])(smem + SM_V);
    float (*QS)[260]  = (float(*)[260])smem;
    float (*Osm)[264] = (float(*)[264])smem;

    const int tid  = threadIdx.x;
    const int warp = tid >> 5;
    const int lane = tid & 31;
    const int lr = lane >> 2;
    const int lc = lane & 3;
    const int br = warp >> 2;
    const int rg = (warp >> 1) & 1;
    const int vh = warp & 1;

    float (*Psm)[36] = (float(*)[36])(smem + SM_P + warp * 576);

    const int bh = blockIdx.y;
    const int b = bh / H_;
    const int h = bh % H_;
    const int kvh = h / REP_;
    const int q0 = blockIdx.x * 32;

    #pragma unroll
    for (int r = 0; r < 8; r++) {
        int idx = tid + 256 * r;
        int qr = idx >> 6;
        int c4 = (idx & 63) * 4;
        float4 v = *(const float4*)&Q[((size_t)(b * T_ + q0 + qr) * H_ + h) * 256 + c4];
        v.x *= SCALE_F; v.y *= SCALE_F; v.z *= SCALE_F; v.w *= SCALE_F;
        *(float4*)&QS[qr][c4] = to_tf32_4(v);
    }
    __syncthreads();

    uint32_t qf[16][4];
    {
        const int r0 = rg * 16 + lr;
        const int cb = br * 128;
        #pragma unroll
        for (int ks = 0; ks < 16; ks++) {
            qf[ks][0] = __float_as_uint(QS[r0]    [cb + ks * 8 + lc]);
            qf[ks][1] = __float_as_uint(QS[r0 + 8][cb + ks * 8 + lc]);
            qf[ks][2] = __float_as_uint(QS[r0]    [cb + ks * 8 + lc + 4]);
            qf[ks][3] = __float_as_uint(QS[r0 + 8][cb + ks * 8 + lc + 4]);
        }
    }

    float oacc[16][4];
    #pragma unroll
    for (int n = 0; n < 16; n++)
        #pragma unroll
        for (int r = 0; r < 4; r++)
            oacc[n][r] = 0.f;
    float m0 = -1e30f, m1 = -1e30f, l0 = 0.f, l1 = 0.f;

    const float (*Ks)[132] = br ? K2s : K1s;
    const int row0 = q0 + rg * 16 + lr;
    const int row1 = row0 + 8;
    const int ntiles = q0 / 32 + 1;

    for (int kt = 0; kt < ntiles; kt++) {
        const int k0 = kt * 32;
        __syncthreads();
        #pragma unroll
        for (int r = 0; r < 8; r++) {
            int idx = tid + 256 * r;
            int j = idx >> 6;
            int c4 = idx & 63;
            size_t kb = ((size_t)(b * T_ + k0 + j) * KVH_ + kvh) * 256;
            float4 kv = to_tf32_4(*(const float4*)&Kg[kb + c4 * 4]);
            if (c4 < 32) *(float4*)&K1s[j][c4 * 4] = kv;
            else         *(float4*)&K2s[j][(c4 - 32) * 4] = kv;
            float4 vv = to_tf32_4(*(const float4*)&Vg[kb + c4 * 4]);
            *(float4*)&Vs[j][c4 * 4] = vv;
        }
        __syncthreads();

        float sf[4][4];
        #pragma unroll
        for (int n = 0; n < 4; n++)
            #pragma unroll
            for (int r = 0; r < 4; r++)
                sf[n][r] = 0.f;
        #pragma unroll
        for (int n = 0; n < 4; n++) {
            #pragma unroll
            for (int ks = 0; ks < 16; ks++) {
                uint32_t bf[2];
                bf[0] = __float_as_uint(Ks[n * 8 + lr][ks * 8 + lc]);
                bf[1] = __float_as_uint(Ks[n * 8 + lr][ks * 8 + lc + 4]);
                mma_tf32(sf[n], qf[ks], bf);
            }
        }

        if (kt == ntiles - 1) {
            #pragma unroll
            for (int n = 0; n < 4; n++) {
                int key = k0 + n * 8 + 2 * lc;
                if (key     > row0) sf[n][0] = -1e30f;
                if (key + 1 > row0) sf[n][1] = -1e30f;
                if (key     > row1) sf[n][2] = -1e30f;
                if (key + 1 > row1) sf[n][3] = -1e30f;
            }
        }

        float mx0 = -1e30f, mx1 = -1e30f;
        #pragma unroll
        for (int n = 0; n < 4; n++) {
            mx0 = fmaxf(mx0, fmaxf(sf[n][0], sf[n][1]));
            mx1 = fmaxf(mx1, fmaxf(sf[n][2], sf[n][3]));
        }
        mx0 = fmaxf(mx0, __shfl_xor_sync(0xffffffffu, mx0, 1));
        mx0 = fmaxf(mx0, __shfl_xor_sync(0xffffffffu, mx0, 2));
        mx1 = fmaxf(mx1, __shfl_xor_sync(0xffffffffu, mx1, 1));
        mx1 = fmaxf(mx1, __shfl_xor_sync(0xffffffffu, mx1, 2));

        float mn0 = fmaxf(m0, mx0), mn1 = fmaxf(m1, mx1);
        float c0 = __expf(m0 - mn0), c1 = __expf(m1 - mn1);
        m0 = mn0; m1 = mn1;

        float rs0 = 0.f, rs1 = 0.f;
        #pragma unroll
        for (int n = 0; n < 4; n++) {
            sf[n][0] = __expf(sf[n][0] - mn0);
            sf[n][1] = __expf(sf[n][1] - mn0);
            sf[n][2] = __expf(sf[n][2] - mn1);
            sf[n][3] = __expf(sf[n][3] - mn1);
            rs0 += sf[n][0] + sf[n][1];
            rs1 += sf[n][2] + sf[n][3];
        }
        rs0 += __shfl_xor_sync(0xffffffffu, rs0, 1);
        rs0 += __shfl_xor_sync(0xffffffffu, rs0, 2);
        rs1 += __shfl_xor_sync(0xffffffffu, rs1, 1);
        rs1 += __shfl_xor_sync(0xffffffffu, rs1, 2);
        l0 = l0 * c0 + rs0;
        l1 = l1 * c1 + rs1;

        #pragma unroll
        for (int n = 0; n < 16; n++) {
            oacc[n][0] *= c0; oacc[n][1] *= c0;
            oacc[n][2] *= c1; oacc[n][3] *= c1;
        }

        __syncwarp();
        #pragma unroll
        for (int n = 0; n < 4; n++) {
            *(float2*)&Psm[lr]    [n * 8 + 2 * lc] =
                make_float2(to_tf32(sf[n][0]), to_tf32(sf[n][1]));
            *(float2*)&Psm[lr + 8][n * 8 + 2 * lc] =
                make_float2(to_tf32(sf[n][2]), to_tf32(sf[n][3]));
        }
        __syncwarp();

        const int vb = vh * 128;
        #pragma unroll
        for (int ks = 0; ks < 4; ks++) {
            uint32_t af[4];
            af[0] = __float_as_uint(Psm[lr]    [ks * 8 + lc]);
            af[1] = __float_as_uint(Psm[lr + 8][ks * 8 + lc]);
            af[2] = __float_as_uint(Psm[lr]    [ks * 8 + lc + 4]);
            af[3] = __float_as_uint(Psm[lr + 8][ks * 8 + lc + 4]);
            #pragma unroll
            for (int n = 0; n < 16; n++) {
                uint32_t bf[2];
                bf[0] = __float_as_uint(Vs[ks * 8 + lc]    [vb + n * 8 + lr]);
                bf[1] = __float_as_uint(Vs[ks * 8 + lc + 4][vb + n * 8 + lr]);
                mma_tf32(oacc[n], af, bf);
            }
        }
    }

    __syncthreads();
    const int orow0 = rg * 16 + lr;
    const int vb = vh * 128;
    if (br == 0) {
        float r0 = 1.f / l0, r1 = 1.f / l1;
        #pragma unroll
        for (int n = 0; n < 16; n++) {
            *(float2*)&Osm[orow0]    [vb + n * 8 + 2 * lc] =
                make_float2(oacc[n][0] * r0, oacc[n][1] * r0);
            *(float2*)&Osm[orow0 + 8][vb + n * 8 + 2 * lc] =
                make_float2(oacc[n][2] * r1, oacc[n][3] * r1);
        }
    }
    __syncthreads();
    if (br == 1) {
        const float lam = g_lambda;
        float r0 = lam / l0, r1 = lam / l1;
        #pragma unroll
        for (int n = 0; n < 16; n++) {
            float2 a0 = *(float2*)&Osm[orow0]    [vb + n * 8 + 2 * lc];
            float2 a1 = *(float2*)&Osm[orow0 + 8][vb + n * 8 + 2 * lc];
            a0.x -= oacc[n][0] * r0; a0.y -= oacc[n][1] * r0;
            a1.x -= oacc[n][2] * r1; a1.y -= oacc[n][3] * r1;
            *(float2*)&Osm[orow0]    [vb + n * 8 + 2 * lc] = a0;
            *(float2*)&Osm[orow0 + 8][vb + n * 8 + 2 * lc] = a1;
        }
    }
    __syncthreads();

    const float4 gw0 = *(const float4*)&gnw[h * 256 + lane * 4];
    const float4 gw1 = *(const float4*)&gnw[h * 256 + 128 + lane * 4];
    const float4 gb0 = *(const float4*)&gnb[h * 256 + lane * 4];
    const float4 gb1 = *(const float4*)&gnb[h * 256 + 128 + lane * 4];
    #pragma unroll
    for (int i = 0; i < 4; i++) {
        int r = warp * 4 + i;
        float4 v0 = *(float4*)&Osm[r][lane * 4];
        float4 v1 = *(float4*)&Osm[r][128 + lane * 4];
        float sum = v0.x + v0.y + v0.z + v0.w + v1.x + v1.y + v1.z + v1.w;
        float ss  = v0.x*v0.x + v0.y*v0.y + v0.z*v0.z + v0.w*v0.w
                  + v1.x*v1.x + v1.y*v1.y + v1.z*v1.z + v1.w*v1.w;
        #pragma unroll
        for (int o = 16; o; o >>= 1) {
            sum += __shfl_xor_sync(0xffffffffu, sum, o);
            ss  += __shfl_xor_sync(0xffffffffu, ss, o);
        }
        float mean = sum * (1.f / 256.f);
        float var = ss * (1.f / 256.f) - mean * mean;
        float rstd = rsqrtf(var + GN_EPS_F);
        float o0x = ((v0.x - mean) * rstd * gw0.x + gb0.x) * ONE_MINUS_LI_F;
        float o0y = ((v0.y - mean) * rstd * gw0.y + gb0.y) * ONE_MINUS_LI_F;
        float o0z = ((v0.z - mean) * rstd * gw0.z + gb0.z) * ONE_MINUS_LI_F;
        float o0w = ((v0.w - mean) * rstd * gw0.w + gb0.w) * ONE_MINUS_LI_F;
        float o1x = ((v1.x - mean) * rstd * gw1.x + gb1.x) * ONE_MINUS_LI_F;
        float o1y = ((v1.y - mean) * rstd * gw1.y + gb1.y) * ONE_MINUS_LI_F;
        float o1z = ((v1.z - mean) * rstd * gw1.z + gb1.z) * ONE_MINUS_LI_F;
        float o1w = ((v1.w - mean) * rstd * gw1.w + gb1.w) * ONE_MINUS_LI_F;
        size_t ob = (size_t)(b * T_ + q0 + r) * 4096 + h * 256;
        *(__half2*)&Oh[ob + lane * 4]           = __floats2half2_rn(o0x, o0y);
        *(__half2*)&Oh[ob + lane * 4 + 2]       = __floats2half2_rn(o0z, o0w);
        *(__half2*)&Oh[ob + 128 + lane * 4]     = __floats2half2_rn(o1x, o1y);
        *(__half2*)&Oh[ob + 128 + lane * 4 + 2] = __floats2half2_rn(o1z, o1w);
    }
}

// ---------------- host launcher -----------------------------------------------
extern "C" void kernel_launch(void* const* d_in, const int* in_sizes, int n_in,
                              void* d_out, int out_size) {
    const float* x   = (const float*)d_in[0];
    const float* Wq  = (const float*)d_in[1];
    const float* Wk  = (const float*)d_in[2];
    const float* Wv  = (const float*)d_in[3];
    const float* Wo  = (const float*)d_in[4];
    const float* lq1 = (const float*)d_in[5];
    const float* lk1 = (const float*)d_in[6];
    const float* lq2 = (const float*)d_in[7];
    const float* lk2 = (const float*)d_in[8];
    const float* gnw = (const float*)d_in[9];
    const float* gnb = (const float*)d_in[10];
    const int*   pos = (const int*)d_in[11];
    float* out = (float*)d_out;

    float *pQ, *pK, *pV;
    __half *pXh, *pWqh, *pWkh, *pWvh, *pWoh, *pOh;
    cudaGetSymbolAddress((void**)&pQ, g_Q);
    cudaGetSymbolAddress((void**)&pK, g_K);
    cudaGetSymbolAddress((void**)&pV, g_V);
    cudaGetSymbolAddress((void**)&pXh, g_Xh);
    cudaGetSymbolAddress((void**)&pWqh, g_Wqh);
    cudaGetSymbolAddress((void**)&pWkh, g_Wkh);
    cudaGetSymbolAddress((void**)&pWvh, g_Wvh);
    cudaGetSymbolAddress((void**)&pWoh, g_Woh);
    cudaGetSymbolAddress((void**)&pOh, g_Oh);

    const int M = B_ * T_;   // 2048
    const int attn_smem = SM_TOTF * 4;  // 86016 B
    cudaFuncSetAttribute(attn_kernel, cudaFuncAttributeMaxDynamicSharedMemorySize, attn_smem);
    cudaFuncSetAttribute(gemm_qkv_h, cudaFuncAttributeMaxDynamicSharedMemorySize, GEMM_SMEM_BYTES);
    cudaFuncSetAttribute(gemm_out_h, cudaFuncAttributeMaxDynamicSharedMemorySize, GEMM_SMEM_BYTES);

    lambda_kernel<<<1, 32>>>(lq1, lk1, lq2, lk2);

    // fp32 -> fp16 conversions
    {
        int n4;
        n4 = (M * D_) / 4;
        f2h_kernel<<<(n4 + 255) / 256, 256>>>(x, pXh, n4);
        n4 = (2 * H_ * DH_ * D_) / 4;
        f2h_kernel<<<(n4 + 255) / 256, 256>>>(Wq, pWqh, n4);
        n4 = (2 * KVH_ * DH_ * D_) / 4;
        f2h_kernel<<<(n4 + 255) / 256, 256>>>(Wk, pWkh, n4);
        f2h_kernel<<<(n4 + 255) / 256, 256>>>(Wv, pWvh, n4);
        n4 = (D_ * 2 * H_ * DH_) / 4;
        f2h_kernel<<<(n4 + 255) / 256, 256>>>(Wo, pWoh, n4);
    }

    // fused Q/K/V projections (fp16 in, fp32 out)
    gemm_qkv_h<<<dim3(48, M / 128), 256, GEMM_SMEM_BYTES>>>(pXh, pWqh, pWkh, pWvh, pQ, pK, pV);

    // RoPE in place
    {
        int npq = M * H_ * 2 * 64;
        int npk = M * KVH_ * 2 * 64;
        rope_kernel<<<(npq + 255) / 256, 256>>>(pQ, pos, 2 * H_, npq);
        rope_kernel<<<(npk + 255) / 256, 256>>>(pK, pos, 2 * KVH_, npk);
    }

    // attention + diff combine + GroupNorm (writes fp16 O)
    attn_kernel<<<dim3(T_ / 32, B_ * H_), 256, attn_smem>>>(pQ, pK, pV, pOh, gnw, gnb);

    // output projection
    gemm_out_h<<<dim3(D_ / 128, M / 128), 256, GEMM_SMEM_BYTES>>>(pOh, pWoh, out, D_, 4096);
}

// round 7
// speedup vs baseline: 4.6116x; 1.4236x over previous
#include <cuda_runtime.h>
#include <cuda_fp16.h>
#include <math.h>
#include <stdint.h>

#define B_  2
#define T_  1024
#define D_  2048
#define H_  16
#define KVH_ 4
#define DH_ 128
#define REP_ 4

#define LAMBDA_INIT_F   0.35550906759096927f
#define ONE_MINUS_LI_F  0.64449093240903073f
#define GN_EPS_F        1e-5f
#define SCALE_F         0.08838834764831845f  // 1/sqrt(128)

// fp16 GEMM pipeline: BK=16, 4 stages, row stride 24 halves
#define BKH  16
#define LDH  24
#define GEMM_SMEM_BYTES (4 * 128 * LDH * 2 * 2)   // 49152 B

// ---------------- scratch ----------------------------------------------------
static __device__ float  g_Q[(size_t)B_*T_*H_*2*DH_];    // fp32 pre-rope
static __device__ float  g_K[(size_t)B_*T_*KVH_*2*DH_];
static __device__ float  g_V[(size_t)B_*T_*KVH_*2*DH_];
static __device__ __half g_Qh[(size_t)B_*T_*H_*2*DH_];   // fp16 roped+scaled
static __device__ __half g_Kh[(size_t)B_*T_*KVH_*2*DH_];
static __device__ __half g_Vh[(size_t)B_*T_*KVH_*2*DH_];
static __device__ __half g_Xh[(size_t)B_*T_*D_];
static __device__ __half g_Wqh[(size_t)2*H_*DH_*D_];
static __device__ __half g_Wkh[(size_t)2*KVH_*DH_*D_];
static __device__ __half g_Wvh[(size_t)2*KVH_*DH_*D_];
static __device__ __half g_Woh[(size_t)D_*2*H_*DH_];
static __device__ __half g_Oh[(size_t)B_*T_*H_*2*DH_];
static __device__ float  g_lambda;

// ---------------- helpers ----------------------------------------------------
__device__ __forceinline__ void mma_f16(float* c, const uint32_t* a, const uint32_t* b) {
    asm volatile(
        "mma.sync.aligned.m16n8k16.row.col.f32.f16.f16.f32 "
        "{%0,%1,%2,%3}, {%4,%5,%6,%7}, {%8,%9}, {%0,%1,%2,%3};"
        : "+f"(c[0]), "+f"(c[1]), "+f"(c[2]), "+f"(c[3])
        : "r"(a[0]), "r"(a[1]), "r"(a[2]), "r"(a[3]), "r"(b[0]), "r"(b[1]));
}
__device__ __forceinline__ void ldsm4(uint32_t* r, uint32_t a) {
    asm volatile("ldmatrix.sync.aligned.m8n8.x4.shared.b16 {%0,%1,%2,%3}, [%4];"
        : "=r"(r[0]), "=r"(r[1]), "=r"(r[2]), "=r"(r[3]) : "r"(a));
}
__device__ __forceinline__ void ldsm4t(uint32_t* r, uint32_t a) {
    asm volatile("ldmatrix.sync.aligned.m8n8.x4.trans.shared.b16 {%0,%1,%2,%3}, [%4];"
        : "=r"(r[0]), "=r"(r[1]), "=r"(r[2]), "=r"(r[3]) : "r"(a));
}
__device__ __forceinline__ void cp_async16(uint32_t smem_dst, const void* gsrc) {
    asm volatile("cp.async.cg.shared.global [%0], [%1], 16;" :: "r"(smem_dst), "l"(gsrc));
}
__device__ __forceinline__ void cp_commit() {
    asm volatile("cp.async.commit_group;" ::: "memory");
}
template <int N>
__device__ __forceinline__ void cp_wait() {
    asm volatile("cp.async.wait_group %0;" :: "n"(N) : "memory");
}

// ---------------- fp32 -> fp16 convert ----------------------------------------
__global__ void f2h_kernel(const float* __restrict__ src, __half* __restrict__ dst, int n4) {
    int i = blockIdx.x * blockDim.x + threadIdx.x;
    if (i >= n4) return;
    float4 v = ((const float4*)src)[i];
    ((__half2*)dst)[2 * i]     = __floats2half2_rn(v.x, v.y);
    ((__half2*)dst)[2 * i + 1] = __floats2half2_rn(v.z, v.w);
}

// ---------------- lambda scalar ----------------------------------------------
__global__ void lambda_kernel(const float* __restrict__ lq1, const float* __restrict__ lk1,
                              const float* __restrict__ lq2, const float* __restrict__ lk2) {
    int lane = threadIdx.x;
    float d1 = 0.f, d2 = 0.f;
    #pragma unroll
    for (int i = 0; i < 4; i++) {
        int idx = lane * 4 + i;
        d1 += lq1[idx] * lk1[idx];
        d2 += lq2[idx] * lk2[idx];
    }
    #pragma unroll
    for (int o = 16; o; o >>= 1) {
        d1 += __shfl_xor_sync(0xffffffffu, d1, o);
        d2 += __shfl_xor_sync(0xffffffffu, d2, o);
    }
    if (lane == 0)
        g_lambda = expf(d1) - expf(d2) + LAMBDA_INIT_F;
}

// ---------------- fp16 m16n8k16 GEMM body (4-stage cp.async) ------------------
__device__ __forceinline__ void gemm_body_h(
    const __half* __restrict__ Ablk, const __half* __restrict__ Bblk,
    float* __restrict__ Cblk, int K, int ldc, __half* smem)
{
    __half (*As)[128][LDH] = (__half(*)[128][LDH])smem;
    __half (*Bs)[128][LDH] = (__half(*)[128][LDH])(smem + 4 * 128 * LDH);

    const int tid  = threadIdx.x;
    const int warp = tid >> 5;
    const int lane = tid & 31;
    const int wm = (warp >> 2) * 64;
    const int wn = (warp & 3) * 32;
    const int lr = lane >> 2;
    const int lc = lane & 3;

    const int l_row = tid >> 1;
    const int l_ch  = (tid & 1) * 8;
    const __half* Ag = Ablk + (size_t)l_row * K + l_ch;
    const __half* Bg = Bblk + (size_t)l_row * K + l_ch;

    uint32_t a_dst[4], b_dst[4];
    #pragma unroll
    for (int s = 0; s < 4; s++) {
        a_dst[s] = (uint32_t)__cvta_generic_to_shared(&As[s][l_row][l_ch]);
        b_dst[s] = (uint32_t)__cvta_generic_to_shared(&Bs[s][l_row][l_ch]);
    }

    float acc[4][4][4];
    #pragma unroll
    for (int mi = 0; mi < 4; mi++)
        #pragma unroll
        for (int ni = 0; ni < 4; ni++)
            #pragma unroll
            for (int r = 0; r < 4; r++)
                acc[mi][ni][r] = 0.f;

    const int nt = K / BKH;

    #pragma unroll
    for (int p = 0; p < 3; p++) {
        cp_async16(a_dst[p], Ag + (size_t)p * BKH);
        cp_async16(b_dst[p], Bg + (size_t)p * BKH);
        cp_commit();
    }

    for (int t = 0; t < nt; t++) {
        cp_wait<2>();
        __syncthreads();
        const int s = t & 3;

        uint32_t af[4][4], bf[4][2];
        #pragma unroll
        for (int mi = 0; mi < 4; mi++) {
            af[mi][0] = *(const uint32_t*)&As[s][wm + mi * 16 + lr]    [2 * lc];
            af[mi][1] = *(const uint32_t*)&As[s][wm + mi * 16 + lr + 8][2 * lc];
            af[mi][2] = *(const uint32_t*)&As[s][wm + mi * 16 + lr]    [2 * lc + 8];
            af[mi][3] = *(const uint32_t*)&As[s][wm + mi * 16 + lr + 8][2 * lc + 8];
        }
        #pragma unroll
        for (int ni = 0; ni < 4; ni++) {
            bf[ni][0] = *(const uint32_t*)&Bs[s][wn + ni * 8 + lr][2 * lc];
            bf[ni][1] = *(const uint32_t*)&Bs[s][wn + ni * 8 + lr][2 * lc + 8];
        }
        #pragma unroll
        for (int mi = 0; mi < 4; mi++)
            #pragma unroll
            for (int ni = 0; ni < 4; ni++)
                mma_f16(acc[mi][ni], af[mi], bf[ni]);

        if (t + 3 < nt) {
            const int sn = (t + 3) & 3;
            cp_async16(a_dst[sn], Ag + (size_t)(t + 3) * BKH);
            cp_async16(b_dst[sn], Bg + (size_t)(t + 3) * BKH);
        }
        cp_commit();
    }

    #pragma unroll
    for (int mi = 0; mi < 4; mi++) {
        #pragma unroll
        for (int ni = 0; ni < 4; ni++) {
            int r0 = wm + mi * 16 + lr;
            int cc = wn + ni * 8 + 2 * lc;
            *(float2*)&Cblk[(size_t)r0 * ldc + cc] =
                make_float2(acc[mi][ni][0], acc[mi][ni][1]);
            *(float2*)&Cblk[(size_t)(r0 + 8) * ldc + cc] =
                make_float2(acc[mi][ni][2], acc[mi][ni][3]);
        }
    }
}

__global__ void __launch_bounds__(256, 2) gemm_qkv_h(const __half* __restrict__ x,
                                                     const __half* __restrict__ Wq,
                                                     const __half* __restrict__ Wk,
                                                     const __half* __restrict__ Wv,
                                                     float* __restrict__ Q,
                                                     float* __restrict__ K,
                                                     float* __restrict__ V) {
    extern __shared__ __half hsmem[];
    const int bx = blockIdx.x;
    const int bm = blockIdx.y * 128;
    const __half* W; float* C; int ldc, bn;
    if (bx < 32)      { W = Wq; C = Q; ldc = 4096; bn = bx * 128; }
    else if (bx < 40) { W = Wk; C = K; ldc = 1024; bn = (bx - 32) * 128; }
    else              { W = Wv; C = V; ldc = 1024; bn = (bx - 40) * 128; }
    gemm_body_h(x + (size_t)bm * D_, W + (size_t)bn * D_,
                C + (size_t)bm * ldc + bn, D_, ldc, hsmem);
}

__global__ void __launch_bounds__(256, 2) gemm_out_h(const __half* __restrict__ A,
                                                     const __half* __restrict__ W,
                                                     float* __restrict__ C,
                                                     int N, int K) {
    extern __shared__ __half hsmem[];
    const int bm = blockIdx.y * 128;
    const int bn = blockIdx.x * 128;
    gemm_body_h(A + (size_t)bm * K, W + (size_t)bn * K,
                C + (size_t)bm * N + bn, K, N, hsmem);
}

// ---------------- RoPE: fp32 in -> fp16 out (optional scale) ------------------
__global__ void rope_h_kernel(const float* __restrict__ X, __half* __restrict__ Xh,
                              const int* __restrict__ pos,
                              int nheads2, int npairs_total, float scale) {
    int idx = blockIdx.x * blockDim.x + threadIdx.x;
    if (idx >= npairs_total) return;
    int i = idx & 63;
    int row = idx >> 6;
    int t = (row / nheads2) % T_;
    float inv = exp2f((float)i * (-13.287712379549449f / 64.0f));
    float ang = (float)pos[t] * inv;
    float s, c;
    sincosf(ang, &s, &c);
    const float* p = X + (size_t)row * 128 + 2 * i;
    float x1 = p[0], x2 = p[1];
    float o1 = (x1 * c - x2 * s) * scale;
    float o2 = (x1 * s + x2 * c) * scale;
    *(__half2*)&Xh[(size_t)row * 128 + 2 * i] = __floats2half2_rn(o1, o2);
}

// ---------------- fp16 tensor-core dual flash attention + GroupNorm -----------
// smem (halves): K1s[32][136] | K2s[32][136] | Vs[32][264] | Psm[8][16][40] | QS[32][264]
// Osm (fp32 [32][264]) aliases K1/K2/Vs region in epilogue.
#define SMH_K1 0
#define SMH_K2 4352
#define SMH_VS 8704
#define SMH_P  17152
#define SMH_QS 22272
#define SMH_TOT 30720      // halves -> 61440 B

__global__ void __launch_bounds__(256, 2) attn_kernel(const __half* __restrict__ Qh,
                                                      const __half* __restrict__ Kh,
                                                      const __half* __restrict__ Vh,
                                                      __half* __restrict__ Oh,
                                                      const float* __restrict__ gnw,
                                                      const float* __restrict__ gnb) {
    extern __shared__ __half hs[];
    __half (*K1s)[136] = (__half(*)[136])(hs + SMH_K1);
    __half (*K2s)[136] = (__half(*)[136])(hs + SMH_K2);
    __half (*Vs)[264]  = (__half(*)[264])(hs + SMH_VS);
    __half (*QS)[264]  = (__half(*)[264])(hs + SMH_QS);
    float  (*Osm)[264] = (float(*)[264])hs;

    const int tid  = threadIdx.x;
    const int warp = tid >> 5;
    const int lane = tid & 31;
    const int lr = lane >> 2;
    const int lc = lane & 3;
    const int br = warp >> 2;        // branch 0/1
    const int rg = (warp >> 1) & 1;  // row group
    const int vh = warp & 1;         // V half

    __half (*Psm)[40] = (__half(*)[40])(hs + SMH_P + warp * 640);

    const int bh = blockIdx.y;
    const int b = bh / H_;
    const int h = bh % H_;
    const int kvh = h / REP_;
    const int q0 = blockIdx.x * 32;

    const uint32_t hsb = (uint32_t)__cvta_generic_to_shared(hs);

    // ldmatrix lane address components
    const int lm_r = (lane & 7) + ((lane >> 3) & 1) * 8;  // row within 16
    const int lm_c8 = (lane >> 4) * 8;                     // 0/8 col split

    // A-frag (QS / Psm): row = base + lm_r, col = colbase + lm_c8
    const uint32_t q_addr0 = hsb + (SMH_QS + (rg * 16 + lm_r) * 264 + br * 128 + lm_c8) * 2;
    const uint32_t p_addr0 = hsb + (SMH_P + warp * 640 + lm_r * 40 + lm_c8) * 2;
    // B-frag K (non-trans): key = (lane>>4)*8 + (lane&7), dim = ((lane>>3)&1)*8
    const int k_key = (lane >> 4) * 8 + (lane & 7);
    const int k_dim = ((lane >> 3) & 1) * 8;
    const uint32_t k_addr0 = hsb + ((br ? SMH_K2 : SMH_K1) + k_key * 136 + k_dim) * 2;
    // B-frag V (trans): key = ((lane>>3)&1)*8 + (lane&7), dim = vb + (lane>>4)*8
    const int v_key = ((lane >> 3) & 1) * 8 + (lane & 7);
    const uint32_t v_addr0 = hsb + (SMH_VS + v_key * 264 + vh * 128 + (lane >> 4) * 8) * 2;

    // ---- stage Q (already roped+scaled fp16) ----
    #pragma unroll
    for (int r = 0; r < 4; r++) {
        int idx = tid + 256 * r;
        int qr = idx >> 5;
        int c8 = (idx & 31) * 8;
        uint4 v = *(const uint4*)&Qh[((size_t)(b * T_ + q0 + qr) * H_ + h) * 256 + c8];
        *(uint4*)&QS[qr][c8] = v;
    }

    float oacc[16][4];
    #pragma unroll
    for (int n = 0; n < 16; n++)
        #pragma unroll
        for (int r = 0; r < 4; r++)
            oacc[n][r] = 0.f;
    float m0 = -1e30f, m1 = -1e30f, l0 = 0.f, l1 = 0.f;

    const int row0 = q0 + rg * 16 + lr;
    const int row1 = row0 + 8;
    const int ntiles = q0 / 32 + 1;

    for (int kt = 0; kt < ntiles; kt++) {
        const int k0 = kt * 32;
        __syncthreads();
        // stage K1|K2|V tiles (fp16, coalesced)
        #pragma unroll
        for (int r = 0; r < 4; r++) {
            int idx = tid + 256 * r;
            int key = idx >> 5;
            int c8 = idx & 31;
            size_t kb = ((size_t)(b * T_ + k0 + key) * KVH_ + kvh) * 256;
            uint4 kv = *(const uint4*)&Kh[kb + c8 * 8];
            if (c8 < 16) *(uint4*)&K1s[key][c8 * 8] = kv;
            else         *(uint4*)&K2s[key][(c8 - 16) * 8] = kv;
            uint4 vv = *(const uint4*)&Vh[kb + c8 * 8];
            *(uint4*)&Vs[key][c8 * 8] = vv;
        }
        __syncthreads();

        // ---- S = Q @ K^T [16 x 32] ----
        float sf[4][4];
        #pragma unroll
        for (int n = 0; n < 4; n++)
            #pragma unroll
            for (int r = 0; r < 4; r++)
                sf[n][r] = 0.f;
        #pragma unroll
        for (int ks = 0; ks < 8; ks++) {
            uint32_t qa[4], kb0[4], kb1[4];
            ldsm4(qa, q_addr0 + ks * 32);
            ldsm4(kb0, k_addr0 + ks * 32);
            ldsm4(kb1, k_addr0 + ks * 32 + 16 * 136 * 2);
            mma_f16(sf[0], qa, kb0);
            mma_f16(sf[1], qa, kb0 + 2);
            mma_f16(sf[2], qa, kb1);
            mma_f16(sf[3], qa, kb1 + 2);
        }

        // ---- causal mask (diagonal tile only) ----
        if (kt == ntiles - 1) {
            #pragma unroll
            for (int n = 0; n < 4; n++) {
                int key = k0 + n * 8 + 2 * lc;
                if (key     > row0) sf[n][0] = -1e30f;
                if (key + 1 > row0) sf[n][1] = -1e30f;
                if (key     > row1) sf[n][2] = -1e30f;
                if (key + 1 > row1) sf[n][3] = -1e30f;
            }
        }

        // ---- online softmax ----
        float mx0 = -1e30f, mx1 = -1e30f;
        #pragma unroll
        for (int n = 0; n < 4; n++) {
            mx0 = fmaxf(mx0, fmaxf(sf[n][0], sf[n][1]));
            mx1 = fmaxf(mx1, fmaxf(sf[n][2], sf[n][3]));
        }
        mx0 = fmaxf(mx0, __shfl_xor_sync(0xffffffffu, mx0, 1));
        mx0 = fmaxf(mx0, __shfl_xor_sync(0xffffffffu, mx0, 2));
        mx1 = fmaxf(mx1, __shfl_xor_sync(0xffffffffu, mx1, 1));
        mx1 = fmaxf(mx1, __shfl_xor_sync(0xffffffffu, mx1, 2));

        float mn0 = fmaxf(m0, mx0), mn1 = fmaxf(m1, mx1);
        float c0 = __expf(m0 - mn0), c1 = __expf(m1 - mn1);
        m0 = mn0; m1 = mn1;

        float rs0 = 0.f, rs1 = 0.f;
        #pragma unroll
        for (int n = 0; n < 4; n++) {
            sf[n][0] = __expf(sf[n][0] - mn0);
            sf[n][1] = __expf(sf[n][1] - mn0);
            sf[n][2] = __expf(sf[n][2] - mn1);
            sf[n][3] = __expf(sf[n][3] - mn1);
            rs0 += sf[n][0] + sf[n][1];
            rs1 += sf[n][2] + sf[n][3];
        }
        rs0 += __shfl_xor_sync(0xffffffffu, rs0, 1);
        rs0 += __shfl_xor_sync(0xffffffffu, rs0, 2);
        rs1 += __shfl_xor_sync(0xffffffffu, rs1, 1);
        rs1 += __shfl_xor_sync(0xffffffffu, rs1, 2);
        l0 = l0 * c0 + rs0;
        l1 = l1 * c1 + rs1;

        #pragma unroll
        for (int n = 0; n < 16; n++) {
            oacc[n][0] *= c0; oacc[n][1] *= c0;
            oacc[n][2] *= c1; oacc[n][3] *= c1;
        }

        // ---- P -> smem (fp16) ----
        __syncwarp();
        #pragma unroll
        for (int n = 0; n < 4; n++) {
            *(__half2*)&Psm[lr]    [n * 8 + 2 * lc] = __floats2half2_rn(sf[n][0], sf[n][1]);
            *(__half2*)&Psm[lr + 8][n * 8 + 2 * lc] = __floats2half2_rn(sf[n][2], sf[n][3]);
        }
        __syncwarp();

        // ---- O += P @ V[:, vh*128 .. +128] ----
        #pragma unroll
        for (int ks = 0; ks < 2; ks++) {
            uint32_t pa[4];
            ldsm4(pa, p_addr0 + ks * 32);
            #pragma unroll
            for (int np = 0; np < 8; np++) {
                uint32_t vb4[4];
                ldsm4t(vb4, v_addr0 + ks * (16 * 264 * 2) + np * 32);
                mma_f16(oacc[np * 2],     pa, vb4);
                mma_f16(oacc[np * 2 + 1], pa, vb4 + 2);
            }
        }
    }

    // ---- epilogue: combine branches, GroupNorm ----
    __syncthreads();
    const int orow0 = rg * 16 + lr;
    const int vb = vh * 128;
    if (br == 0) {
        float r0 = 1.f / l0, r1 = 1.f / l1;
        #pragma unroll
        for (int n = 0; n < 16; n++) {
            *(float2*)&Osm[orow0]    [vb + n * 8 + 2 * lc] =
                make_float2(oacc[n][0] * r0, oacc[n][1] * r0);
            *(float2*)&Osm[orow0 + 8][vb + n * 8 + 2 * lc] =
                make_float2(oacc[n][2] * r1, oacc[n][3] * r1);
        }
    }
    __syncthreads();
    if (br == 1) {
        const float lam = g_lambda;
        float r0 = lam / l0, r1 = lam / l1;
        #pragma unroll
        for (int n = 0; n < 16; n++) {
            float2 a0 = *(float2*)&Osm[orow0]    [vb + n * 8 + 2 * lc];
            float2 a1 = *(float2*)&Osm[orow0 + 8][vb + n * 8 + 2 * lc];
            a0.x -= oacc[n][0] * r0; a0.y -= oacc[n][1] * r0;
            a1.x -= oacc[n][2] * r1; a1.y -= oacc[n][3] * r1;
            *(float2*)&Osm[orow0]    [vb + n * 8 + 2 * lc] = a0;
            *(float2*)&Osm[orow0 + 8][vb + n * 8 + 2 * lc] = a1;
        }
    }
    __syncthreads();

    const float4 gw0 = *(const float4*)&gnw[h * 256 + lane * 4];
    const float4 gw1 = *(const float4*)&gnw[h * 256 + 128 + lane * 4];
    const float4 gb0 = *(const float4*)&gnb[h * 256 + lane * 4];
    const float4 gb1 = *(const float4*)&gnb[h * 256 + 128 + lane * 4];
    #pragma unroll
    for (int i = 0; i < 4; i++) {
        int r = warp * 4 + i;
        float4 v0 = *(float4*)&Osm[r][lane * 4];
        float4 v1 = *(float4*)&Osm[r][128 + lane * 4];
        float sum = v0.x + v0.y + v0.z + v0.w + v1.x + v1.y + v1.z + v1.w;
        float ss  = v0.x*v0.x + v0.y*v0.y + v0.z*v0.z + v0.w*v0.w
                  + v1.x*v1.x + v1.y*v1.y + v1.z*v1.z + v1.w*v1.w;
        #pragma unroll
        for (int o = 16; o; o >>= 1) {
            sum += __shfl_xor_sync(0xffffffffu, sum, o);
            ss  += __shfl_xor_sync(0xffffffffu, ss, o);
        }
        float mean = sum * (1.f / 256.f);
        float var = ss * (1.f / 256.f) - mean * mean;
        float rstd = rsqrtf(var + GN_EPS_F);
        float o0x = ((v0.x - mean) * rstd * gw0.x + gb0.x) * ONE_MINUS_LI_F;
        float o0y = ((v0.y - mean) * rstd * gw0.y + gb0.y) * ONE_MINUS_LI_F;
        float o0z = ((v0.z - mean) * rstd * gw0.z + gb0.z) * ONE_MINUS_LI_F;
        float o0w = ((v0.w - mean) * rstd * gw0.w + gb0.w) * ONE_MINUS_LI_F;
        float o1x = ((v1.x - mean) * rstd * gw1.x + gb1.x) * ONE_MINUS_LI_F;
        float o1y = ((v1.y - mean) * rstd * gw1.y + gb1.y) * ONE_MINUS_LI_F;
        float o1z = ((v1.z - mean) * rstd * gw1.z + gb1.z) * ONE_MINUS_LI_F;
        float o1w = ((v1.w - mean) * rstd * gw1.w + gb1.w) * ONE_MINUS_LI_F;
        size_t ob = (size_t)(b * T_ + q0 + r) * 4096 + h * 256;
        *(__half2*)&Oh[ob + lane * 4]           = __floats2half2_rn(o0x, o0y);
        *(__half2*)&Oh[ob + lane * 4 + 2]       = __floats2half2_rn(o0z, o0w);
        *(__half2*)&Oh[ob + 128 + lane * 4]     = __floats2half2_rn(o1x, o1y);
        *(__half2*)&Oh[ob + 128 + lane * 4 + 2] = __floats2half2_rn(o1z, o1w);
    }
}

// ---------------- host launcher -----------------------------------------------
extern "C" void kernel_launch(void* const* d_in, const int* in_sizes, int n_in,
                              void* d_out, int out_size) {
    const float* x   = (const float*)d_in[0];
    const float* Wq  = (const float*)d_in[1];
    const float* Wk  = (const float*)d_in[2];
    const float* Wv  = (const float*)d_in[3];
    const float* Wo  = (const float*)d_in[4];
    const float* lq1 = (const float*)d_in[5];
    const float* lk1 = (const float*)d_in[6];
    const float* lq2 = (const float*)d_in[7];
    const float* lk2 = (const float*)d_in[8];
    const float* gnw = (const float*)d_in[9];
    const float* gnb = (const float*)d_in[10];
    const int*   pos = (const int*)d_in[11];
    float* out = (float*)d_out;

    float *pQ, *pK, *pV;
    __half *pQh, *pKh, *pVh, *pXh, *pWqh, *pWkh, *pWvh, *pWoh, *pOh;
    cudaGetSymbolAddress((void**)&pQ, g_Q);
    cudaGetSymbolAddress((void**)&pK, g_K);
    cudaGetSymbolAddress((void**)&pV, g_V);
    cudaGetSymbolAddress((void**)&pQh, g_Qh);
    cudaGetSymbolAddress((void**)&pKh, g_Kh);
    cudaGetSymbolAddress((void**)&pVh, g_Vh);
    cudaGetSymbolAddress((void**)&pXh, g_Xh);
    cudaGetSymbolAddress((void**)&pWqh, g_Wqh);
    cudaGetSymbolAddress((void**)&pWkh, g_Wkh);
    cudaGetSymbolAddress((void**)&pWvh, g_Wvh);
    cudaGetSymbolAddress((void**)&pWoh, g_Woh);
    cudaGetSymbolAddress((void**)&pOh, g_Oh);

    const int M = B_ * T_;   // 2048
    const int attn_smem = SMH_TOT * 2;  // 61440 B
    cudaFuncSetAttribute(attn_kernel, cudaFuncAttributeMaxDynamicSharedMemorySize, attn_smem);
    cudaFuncSetAttribute(gemm_qkv_h, cudaFuncAttributeMaxDynamicSharedMemorySize, GEMM_SMEM_BYTES);
    cudaFuncSetAttribute(gemm_out_h, cudaFuncAttributeMaxDynamicSharedMemorySize, GEMM_SMEM_BYTES);

    lambda_kernel<<<1, 32>>>(lq1, lk1, lq2, lk2);

    // fp32 -> fp16 conversions (inputs/weights)
    {
        int n4;
        n4 = (M * D_) / 4;
        f2h_kernel<<<(n4 + 255) / 256, 256>>>(x, pXh, n4);
        n4 = (2 * H_ * DH_ * D_) / 4;
        f2h_kernel<<<(n4 + 255) / 256, 256>>>(Wq, pWqh, n4);
        n4 = (2 * KVH_ * DH_ * D_) / 4;
        f2h_kernel<<<(n4 + 255) / 256, 256>>>(Wk, pWkh, n4);
        f2h_kernel<<<(n4 + 255) / 256, 256>>>(Wv, pWvh, n4);
        n4 = (D_ * 2 * H_ * DH_) / 4;
        f2h_kernel<<<(n4 + 255) / 256, 256>>>(Wo, pWoh, n4);
    }

    // fused Q/K/V projections (fp16 in, fp32 out)
    gemm_qkv_h<<<dim3(48, M / 128), 256, GEMM_SMEM_BYTES>>>(pXh, pWqh, pWkh, pWvh, pQ, pK, pV);

    // RoPE -> fp16 (Q gets softmax scale folded in); V -> fp16
    {
        int npq = M * H_ * 2 * 64;
        int npk = M * KVH_ * 2 * 64;
        rope_h_kernel<<<(npq + 255) / 256, 256>>>(pQ, pQh, pos, 2 * H_, npq, SCALE_F);
        rope_h_kernel<<<(npk + 255) / 256, 256>>>(pK, pKh, pos, 2 * KVH_, npk, 1.0f);
        int n4 = (M * KVH_ * 2 * DH_) / 4;
        f2h_kernel<<<(n4 + 255) / 256, 256>>>(pV, pVh, n4);
    }

    // attention + diff combine + GroupNorm (fp16 in, fp16 out)
    attn_kernel<<<dim3(T_ / 32, B_ * H_), 256, attn_smem>>>(pQh, pKh, pVh, pOh, gnw, gnb);

    // output projection
    gemm_out_h<<<dim3(D_ / 128, M / 128), 256, GEMM_SMEM_BYTES>>>(pOh, pWoh, out, D_, 4096);
}

// round 8
// speedup vs baseline: 5.1020x; 1.1063x over previous
#include <cuda_runtime.h>
#include <cuda_fp16.h>
#include <math.h>
#include <stdint.h>

#define B_  2
#define T_  1024
#define D_  2048
#define H_  16
#define KVH_ 4
#define DH_ 128
#define REP_ 4

#define LAMBDA_INIT_F   0.35550906759096927f
#define ONE_MINUS_LI_F  0.64449093240903073f
#define GN_EPS_F        1e-5f
#define SCALE_F         0.08838834764831845f  // 1/sqrt(128)

// fp16 GEMM pipeline: BK=16, 4 stages, row stride 24 halves
#define BKH  16
#define LDH  24
#define GEMM_SMEM_BYTES (4 * 128 * LDH * 2 * 2)   // 49152 B

// ---------------- scratch ----------------------------------------------------
static __device__ float  g_Q[(size_t)B_*T_*H_*2*DH_];    // fp32 pre-rope
static __device__ float  g_K[(size_t)B_*T_*KVH_*2*DH_];
static __device__ __half g_Qh[(size_t)B_*T_*H_*2*DH_];   // fp16 roped+scaled
static __device__ __half g_Kh[(size_t)B_*T_*KVH_*2*DH_];
static __device__ __half g_Vh[(size_t)B_*T_*KVH_*2*DH_]; // fp16 direct from GEMM
static __device__ __half g_Xh[(size_t)B_*T_*D_];
static __device__ __half g_Wqh[(size_t)2*H_*DH_*D_];
static __device__ __half g_Wkh[(size_t)2*KVH_*DH_*D_];
static __device__ __half g_Wvh[(size_t)2*KVH_*DH_*D_];
static __device__ __half g_Woh[(size_t)D_*2*H_*DH_];
static __device__ __half g_Oh[(size_t)B_*T_*H_*2*DH_];
static __device__ float  g_lambda;

// ---------------- helpers ----------------------------------------------------
__device__ __forceinline__ void mma_f16(float* c, const uint32_t* a, const uint32_t* b) {
    asm volatile(
        "mma.sync.aligned.m16n8k16.row.col.f32.f16.f16.f32 "
        "{%0,%1,%2,%3}, {%4,%5,%6,%7}, {%8,%9}, {%0,%1,%2,%3};"
        : "+f"(c[0]), "+f"(c[1]), "+f"(c[2]), "+f"(c[3])
        : "r"(a[0]), "r"(a[1]), "r"(a[2]), "r"(a[3]), "r"(b[0]), "r"(b[1]));
}
__device__ __forceinline__ void ldsm4(uint32_t* r, uint32_t a) {
    asm volatile("ldmatrix.sync.aligned.m8n8.x4.shared.b16 {%0,%1,%2,%3}, [%4];"
        : "=r"(r[0]), "=r"(r[1]), "=r"(r[2]), "=r"(r[3]) : "r"(a));
}
__device__ __forceinline__ void ldsm4t(uint32_t* r, uint32_t a) {
    asm volatile("ldmatrix.sync.aligned.m8n8.x4.trans.shared.b16 {%0,%1,%2,%3}, [%4];"
        : "=r"(r[0]), "=r"(r[1]), "=r"(r[2]), "=r"(r[3]) : "r"(a));
}
__device__ __forceinline__ void cp_async16(uint32_t smem_dst, const void* gsrc) {
    asm volatile("cp.async.cg.shared.global [%0], [%1], 16;" :: "r"(smem_dst), "l"(gsrc));
}
__device__ __forceinline__ void cp_commit() {
    asm volatile("cp.async.commit_group;" ::: "memory");
}
template <int N>
__device__ __forceinline__ void cp_wait() {
    asm volatile("cp.async.wait_group %0;" :: "n"(N) : "memory");
}

// ---------------- fused fp32 -> fp16 convert for 5 tensors --------------------
#define S0_ 1048576   // x      2048*2048/4
#define S1_ 2097152   // Wq     4096*2048/4
#define S2_ 524288    // Wk
#define S3_ 524288    // Wv
#define S4_ 2097152   // Wo
__global__ void f2h5_kernel(const float* __restrict__ x,  const float* __restrict__ Wq,
                            const float* __restrict__ Wk, const float* __restrict__ Wv,
                            const float* __restrict__ Wo,
                            __half* __restrict__ xh,  __half* __restrict__ Wqh,
                            __half* __restrict__ Wkh, __half* __restrict__ Wvh,
                            __half* __restrict__ Woh) {
    int i = blockIdx.x * blockDim.x + threadIdx.x;
    const float* s; __half* d; int off;
    if (i < S0_)                       { s = x;  d = xh;  off = i; }
    else if (i < S0_ + S1_)            { s = Wq; d = Wqh; off = i - S0_; }
    else if (i < S0_ + S1_ + S2_)      { s = Wk; d = Wkh; off = i - S0_ - S1_; }
    else if (i < S0_ + S1_ + S2_ + S3_){ s = Wv; d = Wvh; off = i - S0_ - S1_ - S2_; }
    else                               { s = Wo; d = Woh; off = i - S0_ - S1_ - S2_ - S3_; }
    float4 v = ((const float4*)s)[off];
    ((__half2*)d)[2 * off]     = __floats2half2_rn(v.x, v.y);
    ((__half2*)d)[2 * off + 1] = __floats2half2_rn(v.z, v.w);
}

// ---------------- lambda scalar ----------------------------------------------
__global__ void lambda_kernel(const float* __restrict__ lq1, const float* __restrict__ lk1,
                              const float* __restrict__ lq2, const float* __restrict__ lk2) {
    int lane = threadIdx.x;
    float d1 = 0.f, d2 = 0.f;
    #pragma unroll
    for (int i = 0; i < 4; i++) {
        int idx = lane * 4 + i;
        d1 += lq1[idx] * lk1[idx];
        d2 += lq2[idx] * lk2[idx];
    }
    #pragma unroll
    for (int o = 16; o; o >>= 1) {
        d1 += __shfl_xor_sync(0xffffffffu, d1, o);
        d2 += __shfl_xor_sync(0xffffffffu, d2, o);
    }
    if (lane == 0)
        g_lambda = expf(d1) - expf(d2) + LAMBDA_INIT_F;
}

// ---------------- fp16 m16n8k16 GEMM body (ldmatrix + 4-stage cp.async) -------
// C[128,128] = A[128,K] @ W[128,K]^T. 8 warps (2M x 4N), warp tile 64x32.
template <bool HALF_OUT>
__device__ __forceinline__ void gemm_body_h(
    const __half* __restrict__ Ablk, const __half* __restrict__ Bblk,
    void* __restrict__ Cblk, int K, int ldc, __half* smem)
{
    const int tid  = threadIdx.x;
    const int warp = tid >> 5;
    const int lane = tid & 31;
    const int wm = (warp >> 2) * 64;
    const int wn = (warp & 3) * 32;
    const int lr = lane >> 2;
    const int lc = lane & 3;

    const int l_row = tid >> 1;
    const int l_ch  = (tid & 1) * 8;
    const __half* Ag = Ablk + (size_t)l_row * K + l_ch;
    const __half* Bg = Bblk + (size_t)l_row * K + l_ch;

    const uint32_t smb = (uint32_t)__cvta_generic_to_shared(smem);
    const uint32_t bofs = 4u * 128u * LDH * 2;   // bytes: B region offset

    uint32_t a_dst[4], b_dst[4];
    #pragma unroll
    for (int s = 0; s < 4; s++) {
        a_dst[s] = smb + (s * 128 * LDH + l_row * LDH + l_ch) * 2;
        b_dst[s] = a_dst[s] + bofs;
    }

    // ldmatrix lane addressing
    const int a_lr  = lane & 15;            // row within 16
    const int a_c8  = (lane >> 4) * 8;      // k 0/8
    const int b_row = (lane & 7) + ((lane >> 4) << 3);  // n within 16
    const int b_k8  = ((lane >> 3) & 1) * 8;

    uint32_t a_lm[4], b_lm[4];
    #pragma unroll
    for (int s = 0; s < 4; s++) {
        a_lm[s] = smb + (s * 128 * LDH + (wm + a_lr) * LDH + a_c8) * 2;
        b_lm[s] = smb + bofs + (s * 128 * LDH + (wn + b_row) * LDH + b_k8) * 2;
    }

    float acc[4][4][4];
    #pragma unroll
    for (int mi = 0; mi < 4; mi++)
        #pragma unroll
        for (int ni = 0; ni < 4; ni++)
            #pragma unroll
            for (int r = 0; r < 4; r++)
                acc[mi][ni][r] = 0.f;

    const int nt = K / BKH;

    #pragma unroll
    for (int p = 0; p < 3; p++) {
        cp_async16(a_dst[p], Ag + (size_t)p * BKH);
        cp_async16(b_dst[p], Bg + (size_t)p * BKH);
        cp_commit();
    }

    for (int t = 0; t < nt; t++) {
        cp_wait<2>();
        __syncthreads();
        const int s = t & 3;

        uint32_t af[4][4], bf[4][2];
        #pragma unroll
        for (int mi = 0; mi < 4; mi++)
            ldsm4(af[mi], a_lm[s] + mi * (16 * LDH * 2));
        {
            uint32_t bt[4];
            ldsm4(bt, b_lm[s]);
            bf[0][0] = bt[0]; bf[0][1] = bt[1]; bf[1][0] = bt[2]; bf[1][1] = bt[3];
            ldsm4(bt, b_lm[s] + 16 * LDH * 2);
            bf[2][0] = bt[0]; bf[2][1] = bt[1]; bf[3][0] = bt[2]; bf[3][1] = bt[3];
        }
        #pragma unroll
        for (int mi = 0; mi < 4; mi++)
            #pragma unroll
            for (int ni = 0; ni < 4; ni++)
                mma_f16(acc[mi][ni], af[mi], bf[ni]);

        if (t + 3 < nt) {
            const int sn = (t + 3) & 3;
            cp_async16(a_dst[sn], Ag + (size_t)(t + 3) * BKH);
            cp_async16(b_dst[sn], Bg + (size_t)(t + 3) * BKH);
        }
        cp_commit();
    }

    #pragma unroll
    for (int mi = 0; mi < 4; mi++) {
        #pragma unroll
        for (int ni = 0; ni < 4; ni++) {
            int r0 = wm + mi * 16 + lr;
            int cc = wn + ni * 8 + 2 * lc;
            if (HALF_OUT) {
                __half* Ch = (__half*)Cblk;
                *(__half2*)&Ch[(size_t)r0 * ldc + cc] =
                    __floats2half2_rn(acc[mi][ni][0], acc[mi][ni][1]);
                *(__half2*)&Ch[(size_t)(r0 + 8) * ldc + cc] =
                    __floats2half2_rn(acc[mi][ni][2], acc[mi][ni][3]);
            } else {
                float* Cf = (float*)Cblk;
                *(float2*)&Cf[(size_t)r0 * ldc + cc] =
                    make_float2(acc[mi][ni][0], acc[mi][ni][1]);
                *(float2*)&Cf[(size_t)(r0 + 8) * ldc + cc] =
                    make_float2(acc[mi][ni][2], acc[mi][ni][3]);
            }
        }
    }
}

// ---------------- fused QKV projection (V -> fp16 direct) ---------------------
__global__ void __launch_bounds__(256, 2) gemm_qkv_h(const __half* __restrict__ x,
                                                     const __half* __restrict__ Wq,
                                                     const __half* __restrict__ Wk,
                                                     const __half* __restrict__ Wv,
                                                     float* __restrict__ Q,
                                                     float* __restrict__ K,
                                                     __half* __restrict__ Vh) {
    extern __shared__ __half hsmem[];
    const int bx = blockIdx.x;
    const int bm = blockIdx.y * 128;
    if (bx < 40) {
        const __half* W; float* C; int ldc, bn;
        if (bx < 32) { W = Wq; C = Q; ldc = 4096; bn = bx * 128; }
        else         { W = Wk; C = K; ldc = 1024; bn = (bx - 32) * 128; }
        gemm_body_h<false>(x + (size_t)bm * D_, W + (size_t)bn * D_,
                           C + (size_t)bm * ldc + bn, D_, ldc, hsmem);
    } else {
        int bn = (bx - 40) * 128;
        gemm_body_h<true>(x + (size_t)bm * D_, Wv + (size_t)bn * D_,
                          Vh + (size_t)bm * 1024 + bn, D_, 1024, hsmem);
    }
}

// ---------------- output projection --------------------------------------------
__global__ void __launch_bounds__(256, 2) gemm_out_h(const __half* __restrict__ A,
                                                     const __half* __restrict__ W,
                                                     float* __restrict__ C,
                                                     int N, int K) {
    extern __shared__ __half hsmem[];
    const int bm = blockIdx.y * 128;
    const int bn = blockIdx.x * 128;
    gemm_body_h<false>(A + (size_t)bm * K, W + (size_t)bn * K,
                       C + (size_t)bm * N + bn, K, N, hsmem);
}

// ---------------- RoPE: fp32 in -> fp16 out (optional scale) ------------------
__global__ void rope_h_kernel(const float* __restrict__ X, __half* __restrict__ Xh,
                              const int* __restrict__ pos,
                              int nheads2, int npairs_total, float scale) {
    int idx = blockIdx.x * blockDim.x + threadIdx.x;
    if (idx >= npairs_total) return;
    int i = idx & 63;
    int row = idx >> 6;
    int t = (row / nheads2) % T_;
    float inv = exp2f((float)i * (-13.287712379549449f / 64.0f));
    float ang = (float)pos[t] * inv;
    float s, c;
    sincosf(ang, &s, &c);
    const float* p = X + (size_t)row * 128 + 2 * i;
    float x1 = p[0], x2 = p[1];
    float o1 = (x1 * c - x2 * s) * scale;
    float o2 = (x1 * s + x2 * c) * scale;
    *(__half2*)&Xh[(size_t)row * 128 + 2 * i] = __floats2half2_rn(o1, o2);
}

// ---------------- fp16 tensor-core dual flash attention + GroupNorm -----------
#define SMH_K1 0
#define SMH_K2 4352
#define SMH_VS 8704
#define SMH_P  17152
#define SMH_QS 22272
#define SMH_TOT 30720      // halves -> 61440 B

__global__ void __launch_bounds__(256, 2) attn_kernel(const __half* __restrict__ Qh,
                                                      const __half* __restrict__ Kh,
                                                      const __half* __restrict__ Vh,
                                                      __half* __restrict__ Oh,
                                                      const float* __restrict__ gnw,
                                                      const float* __restrict__ gnb) {
    extern __shared__ __half hs[];
    __half (*K1s)[136] = (__half(*)[136])(hs + SMH_K1);
    __half (*K2s)[136] = (__half(*)[136])(hs + SMH_K2);
    __half (*Vs)[264]  = (__half(*)[264])(hs + SMH_VS);
    __half (*QS)[264]  = (__half(*)[264])(hs + SMH_QS);
    float  (*Osm)[264] = (float(*)[264])hs;

    const int tid  = threadIdx.x;
    const int warp = tid >> 5;
    const int lane = tid & 31;
    const int lr = lane >> 2;
    const int lc = lane & 3;
    const int br = warp >> 2;
    const int rg = (warp >> 1) & 1;
    const int vh = warp & 1;

    __half (*Psm)[40] = (__half(*)[40])(hs + SMH_P + warp * 640);

    const int bh = blockIdx.y;
    const int b = bh / H_;
    const int h = bh % H_;
    const int kvh = h / REP_;
    const int q0 = blockIdx.x * 32;

    const uint32_t hsb = (uint32_t)__cvta_generic_to_shared(hs);

    const int lm_r = (lane & 7) + ((lane >> 3) & 1) * 8;
    const int lm_c8 = (lane >> 4) * 8;

    const uint32_t q_addr0 = hsb + (SMH_QS + (rg * 16 + lm_r) * 264 + br * 128 + lm_c8) * 2;
    const uint32_t p_addr0 = hsb + (SMH_P + warp * 640 + lm_r * 40 + lm_c8) * 2;
    const int k_key = (lane >> 4) * 8 + (lane & 7);
    const int k_dim = ((lane >> 3) & 1) * 8;
    const uint32_t k_addr0 = hsb + ((br ? SMH_K2 : SMH_K1) + k_key * 136 + k_dim) * 2;
    const int v_key = ((lane >> 3) & 1) * 8 + (lane & 7);
    const uint32_t v_addr0 = hsb + (SMH_VS + v_key * 264 + vh * 128 + (lane >> 4) * 8) * 2;

    #pragma unroll
    for (int r = 0; r < 4; r++) {
        int idx = tid + 256 * r;
        int qr = idx >> 5;
        int c8 = (idx & 31) * 8;
        uint4 v = *(const uint4*)&Qh[((size_t)(b * T_ + q0 + qr) * H_ + h) * 256 + c8];
        *(uint4*)&QS[qr][c8] = v;
    }

    float oacc[16][4];
    #pragma unroll
    for (int n = 0; n < 16; n++)
        #pragma unroll
        for (int r = 0; r < 4; r++)
            oacc[n][r] = 0.f;
    float m0 = -1e30f, m1 = -1e30f, l0 = 0.f, l1 = 0.f;

    const int row0 = q0 + rg * 16 + lr;
    const int row1 = row0 + 8;
    const int ntiles = q0 / 32 + 1;

    for (int kt = 0; kt < ntiles; kt++) {
        const int k0 = kt * 32;
        __syncthreads();
        #pragma unroll
        for (int r = 0; r < 4; r++) {
            int idx = tid + 256 * r;
            int key = idx >> 5;
            int c8 = idx & 31;
            size_t kb = ((size_t)(b * T_ + k0 + key) * KVH_ + kvh) * 256;
            uint4 kv = *(const uint4*)&Kh[kb + c8 * 8];
            if (c8 < 16) *(uint4*)&K1s[key][c8 * 8] = kv;
            else         *(uint4*)&K2s[key][(c8 - 16) * 8] = kv;
            uint4 vv = *(const uint4*)&Vh[kb + c8 * 8];
            *(uint4*)&Vs[key][c8 * 8] = vv;
        }
        __syncthreads();

        float sf[4][4];
        #pragma unroll
        for (int n = 0; n < 4; n++)
            #pragma unroll
            for (int r = 0; r < 4; r++)
                sf[n][r] = 0.f;
        #pragma unroll
        for (int ks = 0; ks < 8; ks++) {
            uint32_t qa[4], kb0[4], kb1[4];
            ldsm4(qa, q_addr0 + ks * 32);
            ldsm4(kb0, k_addr0 + ks * 32);
            ldsm4(kb1, k_addr0 + ks * 32 + 16 * 136 * 2);
            mma_f16(sf[0], qa, kb0);
            mma_f16(sf[1], qa, kb0 + 2);
            mma_f16(sf[2], qa, kb1);
            mma_f16(sf[3], qa, kb1 + 2);
        }

        if (kt == ntiles - 1) {
            #pragma unroll
            for (int n = 0; n < 4; n++) {
                int key = k0 + n * 8 + 2 * lc;
                if (key     > row0) sf[n][0] = -1e30f;
                if (key + 1 > row0) sf[n][1] = -1e30f;
                if (key     > row1) sf[n][2] = -1e30f;
                if (key + 1 > row1) sf[n][3] = -1e30f;
            }
        }

        float mx0 = -1e30f, mx1 = -1e30f;
        #pragma unroll
        for (int n = 0; n < 4; n++) {
            mx0 = fmaxf(mx0, fmaxf(sf[n][0], sf[n][1]));
            mx1 = fmaxf(mx1, fmaxf(sf[n][2], sf[n][3]));
        }
        mx0 = fmaxf(mx0, __shfl_xor_sync(0xffffffffu, mx0, 1));
        mx0 = fmaxf(mx0, __shfl_xor_sync(0xffffffffu, mx0, 2));
        mx1 = fmaxf(mx1, __shfl_xor_sync(0xffffffffu, mx1, 1));
        mx1 = fmaxf(mx1, __shfl_xor_sync(0xffffffffu, mx1, 2));

        float mn0 = fmaxf(m0, mx0), mn1 = fmaxf(m1, mx1);
        float c0 = __expf(m0 - mn0), c1 = __expf(m1 - mn1);
        m0 = mn0; m1 = mn1;

        float rs0 = 0.f, rs1 = 0.f;
        #pragma unroll
        for (int n = 0; n < 4; n++) {
            sf[n][0] = __expf(sf[n][0] - mn0);
            sf[n][1] = __expf(sf[n][1] - mn0);
            sf[n][2] = __expf(sf[n][2] - mn1);
            sf[n][3] = __expf(sf[n][3] - mn1);
            rs0 += sf[n][0] + sf[n][1];
            rs1 += sf[n][2] + sf[n][3];
        }
        rs0 += __shfl_xor_sync(0xffffffffu, rs0, 1);
        rs0 += __shfl_xor_sync(0xffffffffu, rs0, 2);
        rs1 += __shfl_xor_sync(0xffffffffu, rs1, 1);
        rs1 += __shfl_xor_sync(0xffffffffu, rs1, 2);
        l0 = l0 * c0 + rs0;
        l1 = l1 * c1 + rs1;

        #pragma unroll
        for (int n = 0; n < 16; n++) {
            oacc[n][0] *= c0; oacc[n][1] *= c0;
            oacc[n][2] *= c1; oacc[n][3] *= c1;
        }

        __syncwarp();
        #pragma unroll
        for (int n = 0; n < 4; n++) {
            *(__half2*)&Psm[lr]    [n * 8 + 2 * lc] = __floats2half2_rn(sf[n][0], sf[n][1]);
            *(__half2*)&Psm[lr + 8][n * 8 + 2 * lc] = __floats2half2_rn(sf[n][2], sf[n][3]);
        }
        __syncwarp();

        #pragma unroll
        for (int ks = 0; ks < 2; ks++) {
            uint32_t pa[4];
            ldsm4(pa, p_addr0 + ks * 32);
            #pragma unroll
            for (int np = 0; np < 8; np++) {
                uint32_t vb4[4];
                ldsm4t(vb4, v_addr0 + ks * (16 * 264 * 2) + np * 32);
                mma_f16(oacc[np * 2],     pa, vb4);
                mma_f16(oacc[np * 2 + 1], pa, vb4 + 2);
            }
        }
    }

    __syncthreads();
    const int orow0 = rg * 16 + lr;
    const int vb = vh * 128;
    if (br == 0) {
        float r0 = 1.f / l0, r1 = 1.f / l1;
        #pragma unroll
        for (int n = 0; n < 16; n++) {
            *(float2*)&Osm[orow0]    [vb + n * 8 + 2 * lc] =
                make_float2(oacc[n][0] * r0, oacc[n][1] * r0);
            *(float2*)&Osm[orow0 + 8][vb + n * 8 + 2 * lc] =
                make_float2(oacc[n][2] * r1, oacc[n][3] * r1);
        }
    }
    __syncthreads();
    if (br == 1) {
        const float lam = g_lambda;
        float r0 = lam / l0, r1 = lam / l1;
        #pragma unroll
        for (int n = 0; n < 16; n++) {
            float2 a0 = *(float2*)&Osm[orow0]    [vb + n * 8 + 2 * lc];
            float2 a1 = *(float2*)&Osm[orow0 + 8][vb + n * 8 + 2 * lc];
            a0.x -= oacc[n][0] * r0; a0.y -= oacc[n][1] * r0;
            a1.x -= oacc[n][2] * r1; a1.y -= oacc[n][3] * r1;
            *(float2*)&Osm[orow0]    [vb + n * 8 + 2 * lc] = a0;
            *(float2*)&Osm[orow0 + 8][vb + n * 8 + 2 * lc] = a1;
        }
    }
    __syncthreads();

    const float4 gw0 = *(const float4*)&gnw[h * 256 + lane * 4];
    const float4 gw1 = *(const float4*)&gnw[h * 256 + 128 + lane * 4];
    const float4 gb0 = *(const float4*)&gnb[h * 256 + lane * 4];
    const float4 gb1 = *(const float4*)&gnb[h * 256 + 128 + lane * 4];
    #pragma unroll
    for (int i = 0; i < 4; i++) {
        int r = warp * 4 + i;
        float4 v0 = *(float4*)&Osm[r][lane * 4];
        float4 v1 = *(float4*)&Osm[r][128 + lane * 4];
        float sum = v0.x + v0.y + v0.z + v0.w + v1.x + v1.y + v1.z + v1.w;
        float ss  = v0.x*v0.x + v0.y*v0.y + v0.z*v0.z + v0.w*v0.w
                  + v1.x*v1.x + v1.y*v1.y + v1.z*v1.z + v1.w*v1.w;
        #pragma unroll
        for (int o = 16; o; o >>= 1) {
            sum += __shfl_xor_sync(0xffffffffu, sum, o);
            ss  += __shfl_xor_sync(0xffffffffu, ss, o);
        }
        float mean = sum * (1.f / 256.f);
        float var = ss * (1.f / 256.f) - mean * mean;
        float rstd = rsqrtf(var + GN_EPS_F);
        float o0x = ((v0.x - mean) * rstd * gw0.x + gb0.x) * ONE_MINUS_LI_F;
        float o0y = ((v0.y - mean) * rstd * gw0.y + gb0.y) * ONE_MINUS_LI_F;
        float o0z = ((v0.z - mean) * rstd * gw0.z + gb0.z) * ONE_MINUS_LI_F;
        float o0w = ((v0.w - mean) * rstd * gw0.w + gb0.w) * ONE_MINUS_LI_F;
        float o1x = ((v1.x - mean) * rstd * gw1.x + gb1.x) * ONE_MINUS_LI_F;
        float o1y = ((v1.y - mean) * rstd * gw1.y + gb1.y) * ONE_MINUS_LI_F;
        float o1z = ((v1.z - mean) * rstd * gw1.z + gb1.z) * ONE_MINUS_LI_F;
        float o1w = ((v1.w - mean) * rstd * gw1.w + gb1.w) * ONE_MINUS_LI_F;
        size_t ob = (size_t)(b * T_ + q0 + r) * 4096 + h * 256;
        *(__half2*)&Oh[ob + lane * 4]           = __floats2half2_rn(o0x, o0y);
        *(__half2*)&Oh[ob + lane * 4 + 2]       = __floats2half2_rn(o0z, o0w);
        *(__half2*)&Oh[ob + 128 + lane * 4]     = __floats2half2_rn(o1x, o1y);
        *(__half2*)&Oh[ob + 128 + lane * 4 + 2] = __floats2half2_rn(o1z, o1w);
    }
}

// ---------------- host launcher -----------------------------------------------
extern "C" void kernel_launch(void* const* d_in, const int* in_sizes, int n_in,
                              void* d_out, int out_size) {
    const float* x   = (const float*)d_in[0];
    const float* Wq  = (const float*)d_in[1];
    const float* Wk  = (const float*)d_in[2];
    const float* Wv  = (const float*)d_in[3];
    const float* Wo  = (const float*)d_in[4];
    const float* lq1 = (const float*)d_in[5];
    const float* lk1 = (const float*)d_in[6];
    const float* lq2 = (const float*)d_in[7];
    const float* lk2 = (const float*)d_in[8];
    const float* gnw = (const float*)d_in[9];
    const float* gnb = (const float*)d_in[10];
    const int*   pos = (const int*)d_in[11];
    float* out = (float*)d_out;

    float *pQ, *pK;
    __half *pQh, *pKh, *pVh, *pXh, *pWqh, *pWkh, *pWvh, *pWoh, *pOh;
    cudaGetSymbolAddress((void**)&pQ, g_Q);
    cudaGetSymbolAddress((void**)&pK, g_K);
    cudaGetSymbolAddress((void**)&pQh, g_Qh);
    cudaGetSymbolAddress((void**)&pKh, g_Kh);
    cudaGetSymbolAddress((void**)&pVh, g_Vh);
    cudaGetSymbolAddress((void**)&pXh, g_Xh);
    cudaGetSymbolAddress((void**)&pWqh, g_Wqh);
    cudaGetSymbolAddress((void**)&pWkh, g_Wkh);
    cudaGetSymbolAddress((void**)&pWvh, g_Wvh);
    cudaGetSymbolAddress((void**)&pWoh, g_Woh);
    cudaGetSymbolAddress((void**)&pOh, g_Oh);

    const int M = B_ * T_;   // 2048
    const int attn_smem = SMH_TOT * 2;  // 61440 B
    cudaFuncSetAttribute(attn_kernel, cudaFuncAttributeMaxDynamicSharedMemorySize, attn_smem);
    cudaFuncSetAttribute(gemm_qkv_h, cudaFuncAttributeMaxDynamicSharedMemorySize, GEMM_SMEM_BYTES);
    cudaFuncSetAttribute(gemm_out_h, cudaFuncAttributeMaxDynamicSharedMemorySize, GEMM_SMEM_BYTES);

    lambda_kernel<<<1, 32>>>(lq1, lk1, lq2, lk2);

    // fused fp32 -> fp16 conversions (x + 4 weights), one launch
    {
        int total = S0_ + S1_ + S2_ + S3_ + S4_;
        f2h5_kernel<<<(total + 255) / 256, 256>>>(x, Wq, Wk, Wv, Wo,
                                                  pXh, pWqh, pWkh, pWvh, pWoh);
    }

    // fused Q/K/V projections (Q,K fp32 out; V fp16 direct)
    gemm_qkv_h<<<dim3(48, M / 128), 256, GEMM_SMEM_BYTES>>>(pXh, pWqh, pWkh, pWvh, pQ, pK, pVh);

    // RoPE -> fp16 (Q gets softmax scale folded in)
    {
        int npq = M * H_ * 2 * 64;
        int npk = M * KVH_ * 2 * 64;
        rope_h_kernel<<<(npq + 255) / 256, 256>>>(pQ, pQh, pos, 2 * H_, npq, SCALE_F);
        rope_h_kernel<<<(npk + 255) / 256, 256>>>(pK, pKh, pos, 2 * KVH_, npk, 1.0f);
    }

    // attention + diff combine + GroupNorm (fp16 in, fp16 out)
    attn_kernel<<<dim3(T_ / 32, B_ * H_), 256, attn_smem>>>(pQh, pKh, pVh, pOh, gnw, gnb);

    // output projection
    gemm_out_h<<<dim3(D_ / 128, M / 128), 256, GEMM_SMEM_BYTES>>>(pOh, pWoh, out, D_, 4096);
}

// round 10
// speedup vs baseline: 5.4678x; 1.0717x over previous
#include <cuda_runtime.h>
#include <cuda_fp16.h>
#include <math.h>
#include <stdint.h>

#define B_  2
#define T_  1024
#define D_  2048
#define H_  16
#define KVH_ 4
#define DH_ 128
#define REP_ 4

#define LAMBDA_INIT_F   0.35550906759096927f
#define ONE_MINUS_LI_F  0.64449093240903073f
#define GN_EPS_F        1e-5f
#define SCALE_F         0.08838834764831845f  // 1/sqrt(128)
#define ROPE_C          (-13.287712379549449f / 64.0f)   // -log2(10000)/64

// fp16 GEMM pipeline: BK=16, 4 stages, row stride 24 halves
#define BKH  16
#define LDH  24
#define GEMM_SMEM_BYTES (4 * 128 * LDH * 2 * 2)   // 49152 B

// ---------------- scratch ----------------------------------------------------
static __device__ __half g_Qh[(size_t)B_*T_*H_*2*DH_];   // fp16 roped+scaled
static __device__ __half g_Kh[(size_t)B_*T_*KVH_*2*DH_];
static __device__ __half g_Vh[(size_t)B_*T_*KVH_*2*DH_];
static __device__ __half g_Xh[(size_t)B_*T_*D_];
static __device__ __half g_Wqh[(size_t)2*H_*DH_*D_];
static __device__ __half g_Wkh[(size_t)2*KVH_*DH_*D_];
static __device__ __half g_Wvh[(size_t)2*KVH_*DH_*D_];
static __device__ __half g_Woh[(size_t)D_*2*H_*DH_];
static __device__ __half g_Oh[(size_t)B_*T_*H_*2*DH_];
static __device__ float  g_lambda;

// ---------------- helpers ----------------------------------------------------
__device__ __forceinline__ void mma_f16(float* c, const uint32_t* a, const uint32_t* b) {
    asm volatile(
        "mma.sync.aligned.m16n8k16.row.col.f32.f16.f16.f32 "
        "{%0,%1,%2,%3}, {%4,%5,%6,%7}, {%8,%9}, {%0,%1,%2,%3};"
        : "+f"(c[0]), "+f"(c[1]), "+f"(c[2]), "+f"(c[3])
        : "r"(a[0]), "r"(a[1]), "r"(a[2]), "r"(a[3]), "r"(b[0]), "r"(b[1]));
}
__device__ __forceinline__ void ldsm4(uint32_t* r, uint32_t a) {
    asm volatile("ldmatrix.sync.aligned.m8n8.x4.shared.b16 {%0,%1,%2,%3}, [%4];"
        : "=r"(r[0]), "=r"(r[1]), "=r"(r[2]), "=r"(r[3]) : "r"(a));
}
__device__ __forceinline__ void ldsm4t(uint32_t* r, uint32_t a) {
    asm volatile("ldmatrix.sync.aligned.m8n8.x4.trans.shared.b16 {%0,%1,%2,%3}, [%4];"
        : "=r"(r[0]), "=r"(r[1]), "=r"(r[2]), "=r"(r[3]) : "r"(a));
}
__device__ __forceinline__ void cp_async16(uint32_t smem_dst, const void* gsrc) {
    asm volatile("cp.async.cg.shared.global [%0], [%1], 16;" :: "r"(smem_dst), "l"(gsrc));
}
__device__ __forceinline__ void cp_commit() {
    asm volatile("cp.async.commit_group;" ::: "memory");
}
template <int N>
__device__ __forceinline__ void cp_wait() {
    asm volatile("cp.async.wait_group %0;" :: "n"(N) : "memory");
}

// ---------------- fused fp32 -> fp16 convert for 5 tensors --------------------
#define S0_ 1048576
#define S1_ 2097152
#define S2_ 524288
#define S3_ 524288
#define S4_ 2097152
__global__ void f2h5_kernel(const float* __restrict__ x,  const float* __restrict__ Wq,
                            const float* __restrict__ Wk, const float* __restrict__ Wv,
                            const float* __restrict__ Wo,
                            __half* __restrict__ xh,  __half* __restrict__ Wqh,
                            __half* __restrict__ Wkh, __half* __restrict__ Wvh,
                            __half* __restrict__ Woh) {
    int i = blockIdx.x * blockDim.x + threadIdx.x;
    const float* s; __half* d; int off;
    if (i < S0_)                       { s = x;  d = xh;  off = i; }
    else if (i < S0_ + S1_)            { s = Wq; d = Wqh; off = i - S0_; }
    else if (i < S0_ + S1_ + S2_)      { s = Wk; d = Wkh; off = i - S0_ - S1_; }
    else if (i < S0_ + S1_ + S2_ + S3_){ s = Wv; d = Wvh; off = i - S0_ - S1_ - S2_; }
    else                               { s = Wo; d = Woh; off = i - S0_ - S1_ - S2_ - S3_; }
    float4 v = ((const float4*)s)[off];
    ((__half2*)d)[2 * off]     = __floats2half2_rn(v.x, v.y);
    ((__half2*)d)[2 * off + 1] = __floats2half2_rn(v.z, v.w);
}

// ---------------- lambda scalar ----------------------------------------------
__global__ void lambda_kernel(const float* __restrict__ lq1, const float* __restrict__ lk1,
                              const float* __restrict__ lq2, const float* __restrict__ lk2) {
    int lane = threadIdx.x;
    float d1 = 0.f, d2 = 0.f;
    #pragma unroll
    for (int i = 0; i < 4; i++) {
        int idx = lane * 4 + i;
        d1 += lq1[idx] * lk1[idx];
        d2 += lq2[idx] * lk2[idx];
    }
    #pragma unroll
    for (int o = 16; o; o >>= 1) {
        d1 += __shfl_xor_sync(0xffffffffu, d1, o);
        d2 += __shfl_xor_sync(0xffffffffu, d2, o);
    }
    if (lane == 0)
        g_lambda = expf(d1) - expf(d2) + LAMBDA_INIT_F;
}

// ---------------- fp16 m16n8k16 GEMM body (ldmatrix + 4-stage cp.async) -------
// MODE: 0 = fp32 out, 1 = fp16 out, 2 = fp16 out with fused RoPE (+scale)
template <int MODE>
__device__ __forceinline__ void gemm_body_h(
    const __half* __restrict__ Ablk, const __half* __restrict__ Bblk,
    void* __restrict__ Cblk, int K, int ldc, __half* smem,
    const int* __restrict__ pos, int rowbase, int colbase, float scale)
{
    const int tid  = threadIdx.x;
    const int warp = tid >> 5;
    const int lane = tid & 31;
    const int wm = (warp >> 2) * 64;
    const int wn = (warp & 3) * 32;
    const int lr = lane >> 2;
    const int lc = lane & 3;

    const int l_row = tid >> 1;
    const int l_ch  = (tid & 1) * 8;
    const __half* Ag = Ablk + (size_t)l_row * K + l_ch;
    const __half* Bg = Bblk + (size_t)l_row * K + l_ch;

    const uint32_t smb = (uint32_t)__cvta_generic_to_shared(smem);
    const uint32_t bofs = 4u * 128u * LDH * 2;

    uint32_t a_dst[4], b_dst[4];
    #pragma unroll
    for (int s = 0; s < 4; s++) {
        a_dst[s] = smb + (s * 128 * LDH + l_row * LDH + l_ch) * 2;
        b_dst[s] = a_dst[s] + bofs;
    }

    const int a_lr  = lane & 15;
    const int a_c8  = (lane >> 4) * 8;
    const int b_row = (lane & 7) + ((lane >> 4) << 3);
    const int b_k8  = ((lane >> 3) & 1) * 8;

    uint32_t a_lm[4], b_lm[4];
    #pragma unroll
    for (int s = 0; s < 4; s++) {
        a_lm[s] = smb + (s * 128 * LDH + (wm + a_lr) * LDH + a_c8) * 2;
        b_lm[s] = smb + bofs + (s * 128 * LDH + (wn + b_row) * LDH + b_k8) * 2;
    }

    float acc[4][4][4];
    #pragma unroll
    for (int mi = 0; mi < 4; mi++)
        #pragma unroll
        for (int ni = 0; ni < 4; ni++)
            #pragma unroll
            for (int r = 0; r < 4; r++)
                acc[mi][ni][r] = 0.f;

    const int nt = K / BKH;

    #pragma unroll
    for (int p = 0; p < 3; p++) {
        cp_async16(a_dst[p], Ag + (size_t)p * BKH);
        cp_async16(b_dst[p], Bg + (size_t)p * BKH);
        cp_commit();
    }

    for (int t = 0; t < nt; t++) {
        cp_wait<2>();
        __syncthreads();
        const int s = t & 3;

        uint32_t af[4][4], bf[4][2];
        #pragma unroll
        for (int mi = 0; mi < 4; mi++)
            ldsm4(af[mi], a_lm[s] + mi * (16 * LDH * 2));
        {
            uint32_t bt[4];
            ldsm4(bt, b_lm[s]);
            bf[0][0] = bt[0]; bf[0][1] = bt[1]; bf[1][0] = bt[2]; bf[1][1] = bt[3];
            ldsm4(bt, b_lm[s] + 16 * LDH * 2);
            bf[2][0] = bt[0]; bf[2][1] = bt[1]; bf[3][0] = bt[2]; bf[3][1] = bt[3];
        }
        #pragma unroll
        for (int mi = 0; mi < 4; mi++)
            #pragma unroll
            for (int ni = 0; ni < 4; ni++)
                mma_f16(acc[mi][ni], af[mi], bf[ni]);

        if (t + 3 < nt) {
            const int sn = (t + 3) & 3;
            cp_async16(a_dst[sn], Ag + (size_t)(t + 3) * BKH);
            cp_async16(b_dst[sn], Bg + (size_t)(t + 3) * BKH);
        }
        cp_commit();
    }

    #pragma unroll
    for (int mi = 0; mi < 4; mi++) {
        #pragma unroll
        for (int ni = 0; ni < 4; ni++) {
            int r0 = wm + mi * 16 + lr;
            int cc = wn + ni * 8 + 2 * lc;
            if (MODE == 2) {
                __half* Ch = (__half*)Cblk;
                int ip = ((colbase + cc) & 127) >> 1;
                float inv = exp2f((float)ip * ROPE_C);
                int t0 = (rowbase + r0) & (T_ - 1);
                int t1 = (rowbase + r0 + 8) & (T_ - 1);
                float s0, c0, s1, c1;
                sincosf((float)pos[t0] * inv, &s0, &c0);
                sincosf((float)pos[t1] * inv, &s1, &c1);
                float e0 = (acc[mi][ni][0] * c0 - acc[mi][ni][1] * s0) * scale;
                float o0 = (acc[mi][ni][0] * s0 + acc[mi][ni][1] * c0) * scale;
                float e1 = (acc[mi][ni][2] * c1 - acc[mi][ni][3] * s1) * scale;
                float o1 = (acc[mi][ni][2] * s1 + acc[mi][ni][3] * c1) * scale;
                *(__half2*)&Ch[(size_t)r0 * ldc + cc]       = __floats2half2_rn(e0, o0);
                *(__half2*)&Ch[(size_t)(r0 + 8) * ldc + cc] = __floats2half2_rn(e1, o1);
            } else if (MODE == 1) {
                __half* Ch = (__half*)Cblk;
                *(__half2*)&Ch[(size_t)r0 * ldc + cc] =
                    __floats2half2_rn(acc[mi][ni][0], acc[mi][ni][1]);
                *(__half2*)&Ch[(size_t)(r0 + 8) * ldc + cc] =
                    __floats2half2_rn(acc[mi][ni][2], acc[mi][ni][3]);
            } else {
                float* Cf = (float*)Cblk;
                *(float2*)&Cf[(size_t)r0 * ldc + cc] =
                    make_float2(acc[mi][ni][0], acc[mi][ni][1]);
                *(float2*)&Cf[(size_t)(r0 + 8) * ldc + cc] =
                    make_float2(acc[mi][ni][2], acc[mi][ni][3]);
            }
        }
    }
}

// ---------------- fused QKV projection with RoPE epilogue ----------------------
__global__ void __launch_bounds__(256, 2) gemm_qkv_h(const __half* __restrict__ x,
                                                     const __half* __restrict__ Wq,
                                                     const __half* __restrict__ Wk,
                                                     const __half* __restrict__ Wv,
                                                     __half* __restrict__ Qh,
                                                     __half* __restrict__ Kh,
                                                     __half* __restrict__ Vh,
                                                     const int* __restrict__ pos) {
    extern __shared__ __half hsmem[];
    const int bx = blockIdx.x;
    const int bm = blockIdx.y * 128;
    if (bx < 32) {
        int bn = bx * 128;
        gemm_body_h<2>(x + (size_t)bm * D_, Wq + (size_t)bn * D_,
                       Qh + (size_t)bm * 4096 + bn, D_, 4096, hsmem,
                       pos, bm, bn, SCALE_F);
    } else if (bx < 40) {
        int bn = (bx - 32) * 128;
        gemm_body_h<2>(x + (size_t)bm * D_, Wk + (size_t)bn * D_,
                       Kh + (size_t)bm * 1024 + bn, D_, 1024, hsmem,
                       pos, bm, bn, 1.0f);
    } else {
        int bn = (bx - 40) * 128;
        gemm_body_h<1>(x + (size_t)bm * D_, Wv + (size_t)bn * D_,
                       Vh + (size_t)bm * 1024 + bn, D_, 1024, hsmem,
                       nullptr, 0, 0, 1.0f);
    }
}

// ---------------- output projection --------------------------------------------
__global__ void __launch_bounds__(256, 2) gemm_out_h(const __half* __restrict__ A,
                                                     const __half* __restrict__ W,
                                                     float* __restrict__ C,
                                                     int N, int K) {
    extern __shared__ __half hsmem[];
    const int bm = blockIdx.y * 128;
    const int bn = blockIdx.x * 128;
    gemm_body_h<0>(A + (size_t)bm * K, W + (size_t)bn * K,
                   C + (size_t)bm * N + bn, K, N, hsmem,
                   nullptr, 0, 0, 1.0f);
}

// ---------------- fp16 dual flash attention + GroupNorm (cp.async 2-stage) ----
#define SMH_STAGE 17152
#define SMH_K2O   4352
#define SMH_VO    8704
#define SMH_P     34304
#define SMH_QS    39424
#define SMH_TOT   47872

__global__ void __launch_bounds__(256, 2) attn_kernel(const __half* __restrict__ Qh,
                                                      const __half* __restrict__ Kh,
                                                      const __half* __restrict__ Vh,
                                                      __half* __restrict__ Oh,
                                                      const float* __restrict__ gnw,
                                                      const float* __restrict__ gnb) {
    extern __shared__ __half hs[];
    __half (*QS)[264]  = (__half(*)[264])(hs + SMH_QS);
    float  (*Osm)[264] = (float(*)[264])hs;

    const int tid  = threadIdx.x;
    const int warp = tid >> 5;
    const int lane = tid & 31;
    const int lr = lane >> 2;
    const int lc = lane & 3;
    const int br = warp >> 2;
    const int rg = (warp >> 1) & 1;
    const int vh = warp & 1;

    __half (*Psm)[40] = (__half(*)[40])(hs + SMH_P + warp * 640);

    const int bh = blockIdx.y;
    const int b = bh / H_;
    const int h = bh % H_;
    const int kvh = h / REP_;
    const int q0 = (gridDim.x - 1 - blockIdx.x) * 32;

    const uint32_t hsb = (uint32_t)__cvta_generic_to_shared(hs);

    const int lm_r = (lane & 7) + ((lane >> 3) & 1) * 8;
    const int lm_c8 = (lane >> 4) * 8;

    const uint32_t q_addr0 = hsb + (SMH_QS + (rg * 16 + lm_r) * 264 + br * 128 + lm_c8) * 2;
    const uint32_t p_addr0 = hsb + (SMH_P + warp * 640 + lm_r * 40 + lm_c8) * 2;
    const int k_key = (lane >> 4) * 8 + (lane & 7);
    const int k_dim = ((lane >> 3) & 1) * 8;
    const uint32_t k_base = hsb + ((br ? SMH_K2O : 0) + k_key * 136 + k_dim) * 2;
    const int v_key = ((lane >> 3) & 1) * 8 + (lane & 7);
    const uint32_t v_base = hsb + (SMH_VO + v_key * 264 + vh * 128 + (lane >> 4) * 8) * 2;

    // ---- stage Q ----
    #pragma unroll
    for (int r = 0; r < 4; r++) {
        int idx = tid + 256 * r;
        int qr = idx >> 5;
        int c8 = (idx & 31) * 8;
        uint4 v = *(const uint4*)&Qh[((size_t)(b * T_ + q0 + qr) * H_ + h) * 256 + c8];
        *(uint4*)&QS[qr][c8] = v;
    }

    float oacc[16][4];
    #pragma unroll
    for (int n = 0; n < 16; n++)
        #pragma unroll
        for (int r = 0; r < 4; r++)
            oacc[n][r] = 0.f;
    float m0 = -1e30f, m1 = -1e30f, l0 = 0.f, l1 = 0.f;

    const int row0 = q0 + rg * 16 + lr;
    const int row1 = row0 + 8;
    const int ntiles = q0 / 32 + 1;

    auto issue_tile = [&](int kt, int st) {
        const int k0 = kt * 32;
        const uint32_t sb = hsb + st * (SMH_STAGE * 2);
        #pragma unroll
        for (int r = 0; r < 4; r++) {
            int idx = tid + 256 * r;
            int key = idx >> 5;
            int c8 = idx & 31;
            size_t kb = ((size_t)(b * T_ + k0 + key) * KVH_ + kvh) * 256;
            uint32_t kd;
            if (c8 < 16) kd = sb + (key * 136 + c8 * 8) * 2;
            else         kd = sb + (SMH_K2O + key * 136 + (c8 - 16) * 8) * 2;
            cp_async16(kd, &Kh[kb + c8 * 8]);
            cp_async16(sb + (SMH_VO + key * 264 + c8 * 8) * 2, &Vh[kb + c8 * 8]);
        }
    };

    issue_tile(0, 0);
    cp_commit();

    for (int kt = 0; kt < ntiles; kt++) {
        const int k0 = kt * 32;
        const int st = kt & 1;

        // RACE FIX: wait for tile kt, then barrier (all warps done consuming
        // stage st^1 from iteration kt-1), and only THEN overwrite stage st^1.
        cp_wait<0>();
        __syncthreads();
        if (kt + 1 < ntiles) {
            issue_tile(kt + 1, st ^ 1);
            cp_commit();
        }

        const uint32_t soff = st * (SMH_STAGE * 2);
        const uint32_t k_addr0 = k_base + soff;
        const uint32_t v_addr0 = v_base + soff;

        float sf[4][4];
        #pragma unroll
        for (int n = 0; n < 4; n++)
            #pragma unroll
            for (int r = 0; r < 4; r++)
                sf[n][r] = 0.f;
        #pragma unroll
        for (int ks = 0; ks < 8; ks++) {
            uint32_t qa[4], kb0[4], kb1[4];
            ldsm4(qa, q_addr0 + ks * 32);
            ldsm4(kb0, k_addr0 + ks * 32);
            ldsm4(kb1, k_addr0 + ks * 32 + 16 * 136 * 2);
            mma_f16(sf[0], qa, kb0);
            mma_f16(sf[1], qa, kb0 + 2);
            mma_f16(sf[2], qa, kb1);
            mma_f16(sf[3], qa, kb1 + 2);
        }

        if (kt == ntiles - 1) {
            #pragma unroll
            for (int n = 0; n < 4; n++) {
                int key = k0 + n * 8 + 2 * lc;
                if (key     > row0) sf[n][0] = -1e30f;
                if (key + 1 > row0) sf[n][1] = -1e30f;
                if (key     > row1) sf[n][2] = -1e30f;
                if (key + 1 > row1) sf[n][3] = -1e30f;
            }
        }

        float mx0 = -1e30f, mx1 = -1e30f;
        #pragma unroll
        for (int n = 0; n < 4; n++) {
            mx0 = fmaxf(mx0, fmaxf(sf[n][0], sf[n][1]));
            mx1 = fmaxf(mx1, fmaxf(sf[n][2], sf[n][3]));
        }
        mx0 = fmaxf(mx0, __shfl_xor_sync(0xffffffffu, mx0, 1));
        mx0 = fmaxf(mx0, __shfl_xor_sync(0xffffffffu, mx0, 2));
        mx1 = fmaxf(mx1, __shfl_xor_sync(0xffffffffu, mx1, 1));
        mx1 = fmaxf(mx1, __shfl_xor_sync(0xffffffffu, mx1, 2));

        float mn0 = fmaxf(m0, mx0), mn1 = fmaxf(m1, mx1);
        float c0 = __expf(m0 - mn0), c1 = __expf(m1 - mn1);
        m0 = mn0; m1 = mn1;

        float rs0 = 0.f, rs1 = 0.f;
        #pragma unroll
        for (int n = 0; n < 4; n++) {
            sf[n][0] = __expf(sf[n][0] - mn0);
            sf[n][1] = __expf(sf[n][1] - mn0);
            sf[n][2] = __expf(sf[n][2] - mn1);
            sf[n][3] = __expf(sf[n][3] - mn1);
            rs0 += sf[n][0] + sf[n][1];
            rs1 += sf[n][2] + sf[n][3];
        }
        rs0 += __shfl_xor_sync(0xffffffffu, rs0, 1);
        rs0 += __shfl_xor_sync(0xffffffffu, rs0, 2);
        rs1 += __shfl_xor_sync(0xffffffffu, rs1, 1);
        rs1 += __shfl_xor_sync(0xffffffffu, rs1, 2);
        l0 = l0 * c0 + rs0;
        l1 = l1 * c1 + rs1;

        #pragma unroll
        for (int n = 0; n < 16; n++) {
            oacc[n][0] *= c0; oacc[n][1] *= c0;
            oacc[n][2] *= c1; oacc[n][3] *= c1;
        }

        __syncwarp();
        #pragma unroll
        for (int n = 0; n < 4; n++) {
            *(__half2*)&Psm[lr]    [n * 8 + 2 * lc] = __floats2half2_rn(sf[n][0], sf[n][1]);
            *(__half2*)&Psm[lr + 8][n * 8 + 2 * lc] = __floats2half2_rn(sf[n][2], sf[n][3]);
        }
        __syncwarp();

        #pragma unroll
        for (int ks = 0; ks < 2; ks++) {
            uint32_t pa[4];
            ldsm4(pa, p_addr0 + ks * 32);
            #pragma unroll
            for (int np = 0; np < 8; np++) {
                uint32_t vb4[4];
                ldsm4t(vb4, v_addr0 + ks * (16 * 264 * 2) + np * 32);
                mma_f16(oacc[np * 2],     pa, vb4);
                mma_f16(oacc[np * 2 + 1], pa, vb4 + 2);
            }
        }
    }

    // ---- epilogue: combine branches, GroupNorm ----
    __syncthreads();
    const int orow0 = rg * 16 + lr;
    const int vb = vh * 128;
    if (br == 0) {
        float r0 = 1.f / l0, r1 = 1.f / l1;
        #pragma unroll
        for (int n = 0; n < 16; n++) {
            *(float2*)&Osm[orow0]    [vb + n * 8 + 2 * lc] =
                make_float2(oacc[n][0] * r0, oacc[n][1] * r0);
            *(float2*)&Osm[orow0 + 8][vb + n * 8 + 2 * lc] =
                make_float2(oacc[n][2] * r1, oacc[n][3] * r1);
        }
    }
    __syncthreads();
    if (br == 1) {
        const float lam = g_lambda;
        float r0 = lam / l0, r1 = lam / l1;
        #pragma unroll
        for (int n = 0; n < 16; n++) {
            float2 a0 = *(float2*)&Osm[orow0]    [vb + n * 8 + 2 * lc];
            float2 a1 = *(float2*)&Osm[orow0 + 8][vb + n * 8 + 2 * lc];
            a0.x -= oacc[n][0] * r0; a0.y -= oacc[n][1] * r0;
            a1.x -= oacc[n][2] * r1; a1.y -= oacc[n][3] * r1;
            *(float2*)&Osm[orow0]    [vb + n * 8 + 2 * lc] = a0;
            *(float2*)&Osm[orow0 + 8][vb + n * 8 + 2 * lc] = a1;
        }
    }
    __syncthreads();

    const float4 gw0 = *(const float4*)&gnw[h * 256 + lane * 4];
    const float4 gw1 = *(const float4*)&gnw[h * 256 + 128 + lane * 4];
    const float4 gb0 = *(const float4*)&gnb[h * 256 + lane * 4];
    const float4 gb1 = *(const float4*)&gnb[h * 256 + 128 + lane * 4];
    #pragma unroll
    for (int i = 0; i < 4; i++) {
        int r = warp * 4 + i;
        float4 v0 = *(float4*)&Osm[r][lane * 4];
        float4 v1 = *(float4*)&Osm[r][128 + lane * 4];
        float sum = v0.x + v0.y + v0.z + v0.w + v1.x + v1.y + v1.z + v1.w;
        float ss  = v0.x*v0.x + v0.y*v0.y + v0.z*v0.z + v0.w*v0.w
                  + v1.x*v1.x + v1.y*v1.y + v1.z*v1.z + v1.w*v1.w;
        #pragma unroll
        for (int o = 16; o; o >>= 1) {
            sum += __shfl_xor_sync(0xffffffffu, sum, o);
            ss  += __shfl_xor_sync(0xffffffffu, ss, o);
        }
        float mean = sum * (1.f / 256.f);
        float var = ss * (1.f / 256.f) - mean * mean;
        float rstd = rsqrtf(var + GN_EPS_F);
        float o0x = ((v0.x - mean) * rstd * gw0.x + gb0.x) * ONE_MINUS_LI_F;
        float o0y = ((v0.y - mean) * rstd * gw0.y + gb0.y) * ONE_MINUS_LI_F;
        float o0z = ((v0.z - mean) * rstd * gw0.z + gb0.z) * ONE_MINUS_LI_F;
        float o0w = ((v0.w - mean) * rstd * gw0.w + gb0.w) * ONE_MINUS_LI_F;
        float o1x = ((v1.x - mean) * rstd * gw1.x + gb1.x) * ONE_MINUS_LI_F;
        float o1y = ((v1.y - mean) * rstd * gw1.y + gb1.y) * ONE_MINUS_LI_F;
        float o1z = ((v1.z - mean) * rstd * gw1.z + gb1.z) * ONE_MINUS_LI_F;
        float o1w = ((v1.w - mean) * rstd * gw1.w + gb1.w) * ONE_MINUS_LI_F;
        size_t ob = (size_t)(b * T_ + q0 + r) * 4096 + h * 256;
        *(__half2*)&Oh[ob + lane * 4]           = __floats2half2_rn(o0x, o0y);
        *(__half2*)&Oh[ob + lane * 4 + 2]       = __floats2half2_rn(o0z, o0w);
        *(__half2*)&Oh[ob + 128 + lane * 4]     = __floats2half2_rn(o1x, o1y);
        *(__half2*)&Oh[ob + 128 + lane * 4 + 2] = __floats2half2_rn(o1z, o1w);
    }
}

// ---------------- host launcher -----------------------------------------------
extern "C" void kernel_launch(void* const* d_in, const int* in_sizes, int n_in,
                              void* d_out, int out_size) {
    const float* x   = (const float*)d_in[0];
    const float* Wq  = (const float*)d_in[1];
    const float* Wk  = (const float*)d_in[2];
    const float* Wv  = (const float*)d_in[3];
    const float* Wo  = (const float*)d_in[4];
    const float* lq1 = (const float*)d_in[5];
    const float* lk1 = (const float*)d_in[6];
    const float* lq2 = (const float*)d_in[7];
    const float* lk2 = (const float*)d_in[8];
    const float* gnw = (const float*)d_in[9];
    const float* gnb = (const float*)d_in[10];
    const int*   pos = (const int*)d_in[11];
    float* out = (float*)d_out;

    __half *pQh, *pKh, *pVh, *pXh, *pWqh, *pWkh, *pWvh, *pWoh, *pOh;
    cudaGetSymbolAddress((void**)&pQh, g_Qh);
    cudaGetSymbolAddress((void**)&pKh, g_Kh);
    cudaGetSymbolAddress((void**)&pVh, g_Vh);
    cudaGetSymbolAddress((void**)&pXh, g_Xh);
    cudaGetSymbolAddress((void**)&pWqh, g_Wqh);
    cudaGetSymbolAddress((void**)&pWkh, g_Wkh);
    cudaGetSymbolAddress((void**)&pWvh, g_Wvh);
    cudaGetSymbolAddress((void**)&pWoh, g_Woh);
    cudaGetSymbolAddress((void**)&pOh, g_Oh);

    const int M = B_ * T_;   // 2048
    const int attn_smem = SMH_TOT * 2;  // 95744 B
    cudaFuncSetAttribute(attn_kernel, cudaFuncAttributeMaxDynamicSharedMemorySize, attn_smem);
    cudaFuncSetAttribute(gemm_qkv_h, cudaFuncAttributeMaxDynamicSharedMemorySize, GEMM_SMEM_BYTES);
    cudaFuncSetAttribute(gemm_out_h, cudaFuncAttributeMaxDynamicSharedMemorySize, GEMM_SMEM_BYTES);

    lambda_kernel<<<1, 32>>>(lq1, lk1, lq2, lk2);

    {
        int total = S0_ + S1_ + S2_ + S3_ + S4_;
        f2h5_kernel<<<(total + 255) / 256, 256>>>(x, Wq, Wk, Wv, Wo,
                                                  pXh, pWqh, pWkh, pWvh, pWoh);
    }

    gemm_qkv_h<<<dim3(48, M / 128), 256, GEMM_SMEM_BYTES>>>(pXh, pWqh, pWkh, pWvh,
                                                            pQh, pKh, pVh, pos);

    attn_kernel<<<dim3(T_ / 32, B_ * H_), 256, attn_smem>>>(pQh, pKh, pVh, pOh, gnw, gnb);

    gemm_out_h<<<dim3(D_ / 128, M / 128), 256, GEMM_SMEM_BYTES>>>(pOh, pWoh, out, D_, 4096);
}